// round 11
// baseline (speedup 1.0000x reference)
#include <cuda_runtime.h>
#include <math.h>
#include <stdint.h>

#define Bsz 64
#define Ssz 256
#define Hsz 1024
#define BS  16384
#define NCTA 64

__device__ __align__(16) float g_Drw[(size_t)BS * 2048];
__device__ __align__(16) float g_Zp[8 * BS];
__device__ __align__(16) float g_G[BS];
__device__ __align__(256) unsigned g_hT[2][Hsz * Bsz];   // [k][b'] tf32 bits, swizzled
__device__ volatile unsigned g_bar_arrive;
__device__ volatile unsigned g_bar_gen;

#define PA 20
#define PB 132
#define SPW 34

__device__ __forceinline__ unsigned f2tf(float x) {
    unsigned r; asm("cvt.rna.tf32.f32 %0, %1;" : "=r"(r) : "f"(x)); return r;
}
__device__ __forceinline__ void mma8(float* c, const unsigned* a, const unsigned* b) {
    asm volatile("mma.sync.aligned.m16n8k8.row.col.f32.tf32.tf32.f32 "
                 "{%0,%1,%2,%3},{%4,%5,%6,%7},{%8,%9},{%0,%1,%2,%3};"
                 : "+f"(c[0]), "+f"(c[1]), "+f"(c[2]), "+f"(c[3])
                 : "r"(a[0]), "r"(a[1]), "r"(a[2]), "r"(a[3]), "r"(b[0]), "r"(b[1]));
}

__device__ __forceinline__ void tile_mma(const unsigned* sA, const unsigned* sB,
                                         float c[2][8][4], int lane, int wm, int wn) {
    const int q = lane >> 2, la3 = lane & 3;
#pragma unroll
    for (int kk = 0; kk < 16; kk += 8) {
        unsigned a[2][4];
#pragma unroll
        for (int mt = 0; mt < 2; mt++) {
            int r = wm * 32 + mt * 16 + q, cc = kk + la3;
            a[mt][0] = sA[r * PA + cc];     a[mt][1] = sA[(r + 8) * PA + cc];
            a[mt][2] = sA[r * PA + cc + 4]; a[mt][3] = sA[(r + 8) * PA + cc + 4];
        }
        int kx = kk + la3, cb = q * 16 + wn * 8;
        uint4 b0 = *(const uint4*)&sB[kx * PB + cb];
        uint4 b1 = *(const uint4*)&sB[kx * PB + cb + 4];
        uint4 b2 = *(const uint4*)&sB[(kx + 4) * PB + cb];
        uint4 b3 = *(const uint4*)&sB[(kx + 4) * PB + cb + 4];
        unsigned bf[8][2] = {{b0.x,b2.x},{b0.y,b2.y},{b0.z,b2.z},{b0.w,b2.w},
                             {b1.x,b3.x},{b1.y,b3.y},{b1.z,b3.z},{b1.w,b3.w}};
#pragma unroll
        for (int mt = 0; mt < 2; mt++)
#pragma unroll
            for (int nt = 0; nt < 8; nt++) mma8(c[mt][nt], a[mt], bf[nt]);
    }
}

__global__ void init_kernel() {
    int i = blockIdx.x * blockDim.x + threadIdx.x;
    if (i == 0) { g_bar_arrive = 0; g_bar_gen = 0; }
    if (i < 2 * Bsz * Hsz) ((unsigned*)g_hT)[i] = 0u;
}

// ---------------- fused gate + drw GEMM (by<8: gate n-block, by>=8: drw n-block) ----------------
__global__ void __launch_bounds__(256) gemm_kernel(
    const float* __restrict__ D, const float* __restrict__ Q, const float* __restrict__ PM,
    const float* __restrict__ W1, const float* __restrict__ b1, const float* __restrict__ W2,
    const float* __restrict__ Wr, const float* __restrict__ br,
    const float* __restrict__ Wx, const float* __restrict__ bx)
{
    __shared__ __align__(16) unsigned sA[2 * 128 * PA];
    __shared__ __align__(16) unsigned sB[2 * 16 * PB];
    __shared__ float sRed[2][128];
    const int m0 = blockIdx.x * 128;
    const int by = blockIdx.y;
    const int tid = threadIdx.x, lane = tid & 31, wid = tid >> 5, wm = wid & 3, wn = wid >> 2;
    const int am = tid >> 1, ak = (tid & 1) * 8, bk = tid >> 4;
    float c[2][8][4];
#pragma unroll
    for (int i = 0; i < 2; i++)
#pragma unroll
        for (int j = 0; j < 8; j++)
#pragma unroll
            for (int k = 0; k < 4; k++) c[i][j][k] = 0.f;
    float ra[8], rb[8];

    if (by < 8) {
        // ---- gate role ----
        const int n0 = by * 128;
        auto loadAB = [&](int k0) {
            const int qd = k0 >> 10, kk = (k0 & 1023) + ak;
            const int r = m0 + am, b = r >> 8;
            const float4* dp = (const float4*)(D + (size_t)r * Hsz + kk);
            const float4* op = (const float4*)((((qd & 1) == 0) ? Q : PM) + (size_t)b * Hsz + kk);
            float4 d0 = dp[0], d1 = dp[1], o0 = op[0], o1 = op[1];
            if (qd < 2) {
                ra[0] = d0.x * o0.x; ra[1] = d0.y * o0.y; ra[2] = d0.z * o0.z; ra[3] = d0.w * o0.w;
                ra[4] = d1.x * o1.x; ra[5] = d1.y * o1.y; ra[6] = d1.z * o1.z; ra[7] = d1.w * o1.w;
            } else {
                ra[0] = fabsf(d0.x - o0.x); ra[1] = fabsf(d0.y - o0.y); ra[2] = fabsf(d0.z - o0.z); ra[3] = fabsf(d0.w - o0.w);
                ra[4] = fabsf(d1.x - o1.x); ra[5] = fabsf(d1.y - o1.y); ra[6] = fabsf(d1.z - o1.z); ra[7] = fabsf(d1.w - o1.w);
            }
            const float4* wp = (const float4*)(W1 + (size_t)(k0 + bk) * Hsz + n0 + (tid & 15) * 8);
            float4 w0 = wp[0], w1 = wp[1];
            rb[0] = w0.x; rb[1] = w0.y; rb[2] = w0.z; rb[3] = w0.w;
            rb[4] = w1.x; rb[5] = w1.y; rb[6] = w1.z; rb[7] = w1.w;
        };
        auto storeAB = [&](int bsel) {
            unsigned* pA = sA + bsel * 128 * PA;
            unsigned* pB = sB + bsel * 16 * PB;
#pragma unroll
            for (int i = 0; i < 8; i++) pA[am * PA + ak + i] = f2tf(ra[i]);
#pragma unroll
            for (int i = 0; i < 8; i++) pB[bk * PB + i * 16 + (tid & 15)] = f2tf(rb[i]);
        };
        loadAB(0); storeAB(0); __syncthreads();
        int cur = 0;
        for (int k0 = 0; k0 < 4096; k0 += 16) {
            const bool more = (k0 + 16) < 4096;
            if (more) loadAB(k0 + 16);
            tile_mma(sA + cur * 128 * PA, sB + cur * 16 * PB, c, lane, wm, wn);
            if (more) storeAB(cur ^ 1);
            __syncthreads();
            cur ^= 1;
        }
#pragma unroll
        for (int mt = 0; mt < 2; mt++) {
            float s0 = 0.f, s1 = 0.f;
#pragma unroll
            for (int nt = 0; nt < 8; nt++) {
                int nc = n0 + wn * 64 + nt * 8 + (lane & 3) * 2;
                float bb0 = b1[nc], bb1 = b1[nc + 1];
                float w0 = W2[nc], w1 = W2[nc + 1];
                s0 += tanhf(c[mt][nt][0] + bb0) * w0 + tanhf(c[mt][nt][1] + bb1) * w1;
                s1 += tanhf(c[mt][nt][2] + bb0) * w0 + tanhf(c[mt][nt][3] + bb1) * w1;
            }
            s0 += __shfl_xor_sync(0xffffffffu, s0, 1); s0 += __shfl_xor_sync(0xffffffffu, s0, 2);
            s1 += __shfl_xor_sync(0xffffffffu, s1, 1); s1 += __shfl_xor_sync(0xffffffffu, s1, 2);
            if ((lane & 3) == 0) {
                int rl = wm * 32 + mt * 16 + (lane >> 2);
                sRed[wn][rl] = s0; sRed[wn][rl + 8] = s1;
            }
        }
        __syncthreads();
        if (tid < 128) g_Zp[by * BS + m0 + tid] = sRed[0][tid] + sRed[1][tid];
    } else {
        // ---- drw role ----
        const int n0g = (by - 8) * 128;
        const float* W = (n0g < 1024) ? Wr : Wx;
        const float* bias = (n0g < 1024) ? br : bx;
        const int n0 = n0g & 1023;
        auto loadAB = [&](int k0) {
            const float4* dp = (const float4*)(D + (size_t)(m0 + am) * Hsz + k0 + ak);
            float4 d0 = dp[0], d1 = dp[1];
            ra[0] = d0.x; ra[1] = d0.y; ra[2] = d0.z; ra[3] = d0.w;
            ra[4] = d1.x; ra[5] = d1.y; ra[6] = d1.z; ra[7] = d1.w;
            const float4* wp = (const float4*)(W + (size_t)(k0 + bk) * Hsz + n0 + (tid & 15) * 8);
            float4 w0 = wp[0], w1 = wp[1];
            rb[0] = w0.x; rb[1] = w0.y; rb[2] = w0.z; rb[3] = w0.w;
            rb[4] = w1.x; rb[5] = w1.y; rb[6] = w1.z; rb[7] = w1.w;
        };
        auto storeAB = [&](int bsel) {
            unsigned* pA = sA + bsel * 128 * PA;
            unsigned* pB = sB + bsel * 16 * PB;
#pragma unroll
            for (int i = 0; i < 8; i++) pA[am * PA + ak + i] = f2tf(ra[i]);
#pragma unroll
            for (int i = 0; i < 8; i++) pB[bk * PB + i * 16 + (tid & 15)] = f2tf(rb[i]);
        };
        loadAB(0); storeAB(0); __syncthreads();
        int cur = 0;
        for (int k0 = 0; k0 < 1024; k0 += 16) {
            const bool more = (k0 + 16) < 1024;
            if (more) loadAB(k0 + 16);
            tile_mma(sA + cur * 128 * PA, sB + cur * 16 * PB, c, lane, wm, wn);
            if (more) storeAB(cur ^ 1);
            __syncthreads();
            cur ^= 1;
        }
#pragma unroll
        for (int mt = 0; mt < 2; mt++)
#pragma unroll
            for (int nt = 0; nt < 8; nt++) {
                int nl = wn * 64 + nt * 8 + (lane & 3) * 2;
                int r0 = m0 + wm * 32 + mt * 16 + (lane >> 2);
                float bb0 = bias[n0 + nl], bb1 = bias[n0 + nl + 1];
                *(float2*)&g_Drw[(size_t)r0 * 2048 + n0g + nl] = make_float2(c[mt][nt][0] + bb0, c[mt][nt][1] + bb1);
                *(float2*)&g_Drw[(size_t)(r0 + 8) * 2048 + n0g + nl] = make_float2(c[mt][nt][2] + bb0, c[mt][nt][3] + bb1);
            }
    }
}

__global__ void __launch_bounds__(256) softmax_kernel() {
    __shared__ float red[256];
    const int b = blockIdx.x, s = threadIdx.x;
    float v = 0.f;
#pragma unroll
    for (int p = 0; p < 8; p++) v += g_Zp[p * BS + b * Ssz + s];
    red[s] = v; __syncthreads();
    for (int o = 128; o > 0; o >>= 1) { if (s < o) red[s] = fmaxf(red[s], red[s + o]); __syncthreads(); }
    float mx = red[0]; __syncthreads();
    float e = expf(v - mx);
    red[s] = e; __syncthreads();
    for (int o = 128; o > 0; o >>= 1) { if (s < o) red[s] += red[s + o]; __syncthreads(); }
    g_G[b * Ssz + s] = e / red[0];
}

// ---------------- persistent scan: R6 champion (2x32KB ring, 8 chunks) ----------------
#define SCAN_WORDS (16384 + 1024 * SPW + 64 * 33 + 32 + 4)
#define SCAN_SMEM  (SCAN_WORDS * 4 + 1024)

__device__ __forceinline__ void gbar() {
    __threadfence();
    __syncthreads();
    if (threadIdx.x == 0) {
        unsigned gen = g_bar_gen;
        if (atomicAdd((unsigned*)&g_bar_arrive, 1u) == NCTA - 1) {
            g_bar_arrive = 0;
            __threadfence();
            g_bar_gen = gen + 1;
        } else {
            while (g_bar_gen == gen) __nanosleep(32);
            __threadfence();
        }
    }
    __syncthreads();
}

__global__ void __launch_bounds__(256, 1) scan_kernel(
    const float* __restrict__ Ur, const float* __restrict__ U,
    const float* __restrict__ bur, const float* __restrict__ bu,
    float* __restrict__ hs)
{
    extern __shared__ __align__(16) unsigned dynraw[];
    unsigned* dyn = (unsigned*)(((uintptr_t)dynraw + 1023) & ~(uintptr_t)1023);
    unsigned* ring = dyn;
    unsigned* sW = dyn + 16384;
    float* sP = (float*)(sW + 1024 * SPW);
    float* sBias = sP + 64 * 33;
    unsigned mb0 = (unsigned)__cvta_generic_to_shared(sBias + 32);
    unsigned ring_u32 = (unsigned)__cvta_generic_to_shared(ring);

    const int j = blockIdx.x, tid = threadIdx.x, lane = tid & 31, wid = tid >> 5;
    const int wm = wid & 3, wn = wid >> 2, q = lane >> 2, la3 = lane & 3;

    for (int idx = tid; idx < 32 * 1024; idx += 256) {
        int n = idx & 31, k = idx >> 5;
        float v = (n < 16) ? Ur[(size_t)k * Hsz + j * 16 + n]
                           : U[(size_t)k * Hsz + j * 16 + (n - 16)];
        sW[k * SPW + (n & 7) * 4 + (n >> 3)] = f2tf(v);
    }
    if (tid < 16)      sBias[tid] = bur[j * 16 + tid];
    else if (tid < 32) sBias[tid] = bu[j * 16 + tid - 16];
    if (tid == 0) {
        asm volatile("mbarrier.init.shared.b64 [%0], 1;" :: "r"(mb0) : "memory");
        asm volatile("mbarrier.init.shared.b64 [%0], 1;" :: "r"(mb0 + 8) : "memory");
        asm volatile("fence.proxy.async.shared::cta;" ::: "memory");
    }
    __syncthreads();

    const int b_e = tid >> 2, c4 = (tid & 3) * 4;
    const int bpr = (b_e & 7) * 8 + (b_e >> 3);
    const int a_col = ((q * 8 + 2 * wm) ^ (la3 << 1));
    const int bcol = q * 4 + wn * 2;
    float hh[4] = {0.f, 0.f, 0.f, 0.f};
    int ph[2] = {0, 0};

    for (int t = 0; t < Ssz; t++) {
        const unsigned* hsrc = g_hT[(t & 1) ^ 1];
        if (tid == 0) {
            asm volatile("mbarrier.arrive.expect_tx.shared.b64 _, [%0], 32768;" :: "r"(mb0) : "memory");
            asm volatile("cp.async.bulk.shared::cta.global.mbarrier::complete_tx::bytes [%0], [%1], 32768, [%2];"
                         :: "r"(ring_u32), "l"(hsrc), "r"(mb0) : "memory");
        }
        const size_t rd = (size_t)b_e * Ssz + t;
        float4 dr4 = __ldcg((const float4*)(g_Drw + rd * 2048 + j * 16 + c4));
        float4 dw4 = __ldcg((const float4*)(g_Drw + rd * 2048 + 1024 + j * 16 + c4));
        float gt = __ldcg(g_G + rd);

        float acc[2][4] = {{0.f, 0.f, 0.f, 0.f}, {0.f, 0.f, 0.f, 0.f}};
        for (int cch = 0; cch < 8; cch++) {
            if (cch < 7 && tid == 0) {
                int b2 = (cch + 1) & 1;
                asm volatile("mbarrier.arrive.expect_tx.shared.b64 _, [%0], 32768;" :: "r"(mb0 + b2 * 8) : "memory");
                asm volatile("cp.async.bulk.shared::cta.global.mbarrier::complete_tx::bytes [%0], [%1], 32768, [%2];"
                             :: "r"(ring_u32 + b2 * 32768), "l"(hsrc + (cch + 1) * 8192), "r"(mb0 + b2 * 8) : "memory");
            }
            int buf = cch & 1;
            {
                unsigned mba = mb0 + buf * 8;
                unsigned par = (unsigned)ph[buf];
                asm volatile(
                    "{\n\t.reg .pred P1;\n\t"
                    "WL_%=:\n\t"
                    "mbarrier.try_wait.parity.acquire.cta.shared::cta.b64 P1, [%0], %1, 0x989680;\n\t"
                    "@P1 bra.uni WD_%=;\n\t"
                    "bra.uni WL_%=;\n\t"
                    "WD_%=:\n\t}"
                    :: "r"(mba), "r"(par) : "memory");
                ph[buf] ^= 1;
            }
            const unsigned* cb = ring + buf * 8192;
#pragma unroll
            for (int ks = 0; ks < 16; ks++) {
                int kl = ks * 8;
                uint2 A0 = *(const uint2*)&cb[(kl + la3) * 64 + a_col];
                uint2 A1 = *(const uint2*)&cb[(kl + la3 + 4) * 64 + a_col];
                unsigned a[4] = {A0.x, A0.y, A1.x, A1.y};
                int kg = cch * 128 + kl + la3;
                uint2 B0 = *(const uint2*)&sW[kg * SPW + bcol];
                uint2 B1 = *(const uint2*)&sW[(kg + 4) * SPW + bcol];
                unsigned bf0[2] = {B0.x, B1.x}, bf1[2] = {B0.y, B1.y};
                mma8(acc[0], a, bf0);
                mma8(acc[1], a, bf1);
            }
            __syncthreads();
        }
        {
            int r = wm * 16 + q;
            int c0 = wn * 16 + 2 * la3, c1 = c0 + 8;
            sP[r * 33 + c0] = acc[0][0]; sP[r * 33 + c0 + 1] = acc[0][1];
            sP[(r + 8) * 33 + c0] = acc[0][2]; sP[(r + 8) * 33 + c0 + 1] = acc[0][3];
            sP[r * 33 + c1] = acc[1][0]; sP[r * 33 + c1 + 1] = acc[1][1];
            sP[(r + 8) * 33 + c1] = acc[1][2]; sP[(r + 8) * 33 + c1 + 1] = acc[1][3];
        }
        __syncthreads();
        {
            float dr[4] = {dr4.x, dr4.y, dr4.z, dr4.w};
            float dw[4] = {dw4.x, dw4.y, dw4.z, dw4.w};
            float4 ho; float* hop = &ho.x;
            unsigned* dstT = g_hT[t & 1];
#pragma unroll
            for (int i = 0; i < 4; i++) {
                int cc = c4 + i;
                float r = 1.f / (1.f + expf(-(dr[i] + sP[b_e * 33 + cc] + sBias[cc])));
                float ht = tanhf(dw[i] + r * (sP[b_e * 33 + 16 + cc] + sBias[16 + cc]));
                hh[i] = gt * ht + (1.f - gt) * hh[i];
                hop[i] = hh[i];
                dstT[(size_t)(j * 16 + cc) * 64 + (bpr ^ (i << 1))] = f2tf(hh[i]);
            }
            *(float4*)&hs[rd * Hsz + j * 16 + c4] = ho;
        }
        gbar();
    }
}

// ---------------- next_mem ----------------
__global__ void __launch_bounds__(256) nextmem_kernel(
    const float* __restrict__ PM, const float* __restrict__ Q,
    const float* __restrict__ Wm, const float* __restrict__ bm,
    float* __restrict__ out, const float* __restrict__ hs)
{
    __shared__ float sW6[64 * 16];
    __shared__ float sC[64 * 65];
    const int j = blockIdx.x, tid = threadIdx.x;
    const int n = tid & 15, brow = tid >> 4;
    float acc[4] = {0.f, 0.f, 0.f, 0.f};
    for (int k0 = 0; k0 < 3072; k0 += 64) {
        sW6[tid] = Wm[(size_t)(k0 + (tid >> 4)) * Hsz + j * 16 + (tid & 15)];
        sW6[tid + 256] = Wm[(size_t)(k0 + 16 + (tid >> 4)) * Hsz + j * 16 + (tid & 15)];
        sW6[tid + 512] = Wm[(size_t)(k0 + 32 + (tid >> 4)) * Hsz + j * 16 + (tid & 15)];
        sW6[tid + 768] = Wm[(size_t)(k0 + 48 + (tid >> 4)) * Hsz + j * 16 + (tid & 15)];
#pragma unroll
        for (int it = 0; it < 16; it++) {
            int idx = tid + 256 * it;
            int b = idx >> 6, kk = idx & 63, k = k0 + kk;
            float v = (k < 1024) ? PM[b * Hsz + k]
                    : (k < 2048) ? hs[((size_t)b * Ssz + 255) * Hsz + k - 1024]
                                 : Q[b * Hsz + k - 2048];
            sC[b * 65 + kk] = v;
        }
        __syncthreads();
#pragma unroll 8
        for (int kk = 0; kk < 64; kk++) {
            float w = sW6[kk * 16 + n];
            acc[0] += sC[brow * 65 + kk] * w;
            acc[1] += sC[(brow + 16) * 65 + kk] * w;
            acc[2] += sC[(brow + 32) * 65 + kk] * w;
            acc[3] += sC[(brow + 48) * 65 + kk] * w;
        }
        __syncthreads();
    }
    float bb = bm[j * 16 + n];
    out[(size_t)brow * Hsz + j * 16 + n]        = fmaxf(acc[0] + bb, 0.f);
    out[(size_t)(brow + 16) * Hsz + j * 16 + n] = fmaxf(acc[1] + bb, 0.f);
    out[(size_t)(brow + 32) * Hsz + j * 16 + n] = fmaxf(acc[2] + bb, 0.f);
    out[(size_t)(brow + 48) * Hsz + j * 16 + n] = fmaxf(acc[3] + bb, 0.f);
}

extern "C" void kernel_launch(void* const* d_in, const int* in_sizes, int n_in,
                              void* d_out, int out_size) {
    const float* D   = (const float*)d_in[0];
    const float* Q   = (const float*)d_in[1];
    const float* PM  = (const float*)d_in[2];
    const float* Wr  = (const float*)d_in[3];
    const float* br  = (const float*)d_in[4];
    const float* Ur  = (const float*)d_in[5];
    const float* bur = (const float*)d_in[6];
    const float* Wx  = (const float*)d_in[7];
    const float* bx  = (const float*)d_in[8];
    const float* U   = (const float*)d_in[9];
    const float* bu  = (const float*)d_in[10];
    const float* W1  = (const float*)d_in[11];
    const float* b1  = (const float*)d_in[12];
    const float* W2  = (const float*)d_in[13];
    const float* Wm  = (const float*)d_in[15];
    const float* bm  = (const float*)d_in[16];
    float* out = (float*)d_out;

    static int attr_done = 0;
    if (!attr_done) {
        cudaFuncSetAttribute(scan_kernel, cudaFuncAttributeMaxDynamicSharedMemorySize, SCAN_SMEM);
        attr_done = 1;
    }

    init_kernel<<<512, 256>>>();
    gemm_kernel<<<dim3(128, 24), 256>>>(D, Q, PM, W1, b1, W2, Wr, br, Wx, bx);
    softmax_kernel<<<64, 256>>>();
    scan_kernel<<<NCTA, 256, SCAN_SMEM>>>(Ur, U, bur, bu, out + Bsz * Hsz);
    nextmem_kernel<<<64, 256>>>(PM, Q, Wm, bm, out, out + Bsz * Hsz);
}

// round 12
// speedup vs baseline: 1.3136x; 1.3136x over previous
#include <cuda_runtime.h>
#include <cuda_fp16.h>
#include <math.h>
#include <stdint.h>

#define Bsz 64
#define Ssz 256
#define Hsz 1024
#define BS  16384
#define NCTA 64

__device__ __align__(16) float g_Drw[(size_t)BS * 2048];
__device__ __align__(16) float g_Zp[8 * BS];
__device__ __align__(16) float g_G[BS];
__device__ __align__(256) unsigned g_h2[2][8][4096];   // [buf][chunk][b*64 + swizzled k-word], fp16x2
__device__ volatile unsigned g_bar_arrive;
__device__ volatile unsigned g_bar_gen;

#define PA 20
#define PB 132
#define SWROW 512

__device__ __forceinline__ unsigned f2tf(float x) {
    unsigned r; asm("cvt.rna.tf32.f32 %0, %1;" : "=r"(r) : "f"(x)); return r;
}
__device__ __forceinline__ void mma8(float* c, const unsigned* a, const unsigned* b) {
    asm volatile("mma.sync.aligned.m16n8k8.row.col.f32.tf32.tf32.f32 "
                 "{%0,%1,%2,%3},{%4,%5,%6,%7},{%8,%9},{%0,%1,%2,%3};"
                 : "+f"(c[0]), "+f"(c[1]), "+f"(c[2]), "+f"(c[3])
                 : "r"(a[0]), "r"(a[1]), "r"(a[2]), "r"(a[3]), "r"(b[0]), "r"(b[1]));
}
__device__ __forceinline__ void mmah(float* c, const unsigned* a, const unsigned* b) {
    asm volatile("mma.sync.aligned.m16n8k16.row.col.f32.f16.f16.f32 "
                 "{%0,%1,%2,%3},{%4,%5,%6,%7},{%8,%9},{%0,%1,%2,%3};"
                 : "+f"(c[0]), "+f"(c[1]), "+f"(c[2]), "+f"(c[3])
                 : "r"(a[0]), "r"(a[1]), "r"(a[2]), "r"(a[3]), "r"(b[0]), "r"(b[1]));
}

__device__ __forceinline__ void tile_mma(const unsigned* sA, const unsigned* sB,
                                         float c[2][8][4], int lane, int wm, int wn) {
    const int q = lane >> 2, la3 = lane & 3;
#pragma unroll
    for (int kk = 0; kk < 16; kk += 8) {
        unsigned a[2][4];
#pragma unroll
        for (int mt = 0; mt < 2; mt++) {
            int r = wm * 32 + mt * 16 + q, cc = kk + la3;
            a[mt][0] = sA[r * PA + cc];     a[mt][1] = sA[(r + 8) * PA + cc];
            a[mt][2] = sA[r * PA + cc + 4]; a[mt][3] = sA[(r + 8) * PA + cc + 4];
        }
        int kx = kk + la3, cb = q * 16 + wn * 8;
        uint4 b0 = *(const uint4*)&sB[kx * PB + cb];
        uint4 b1 = *(const uint4*)&sB[kx * PB + cb + 4];
        uint4 b2 = *(const uint4*)&sB[(kx + 4) * PB + cb];
        uint4 b3 = *(const uint4*)&sB[(kx + 4) * PB + cb + 4];
        unsigned bf[8][2] = {{b0.x,b2.x},{b0.y,b2.y},{b0.z,b2.z},{b0.w,b2.w},
                             {b1.x,b3.x},{b1.y,b3.y},{b1.z,b3.z},{b1.w,b3.w}};
#pragma unroll
        for (int mt = 0; mt < 2; mt++)
#pragma unroll
            for (int nt = 0; nt < 8; nt++) mma8(c[mt][nt], a[mt], bf[nt]);
    }
}

__global__ void init_kernel() {
    int i = blockIdx.x * blockDim.x + threadIdx.x;
    if (i == 0) { g_bar_arrive = 0; g_bar_gen = 0; }
    if (i < 2 * 8 * 4096) ((unsigned*)g_h2)[i] = 0u;
}

// ---------------- gate GEMM ----------------
__global__ void __launch_bounds__(256) gate_kernel(
    const float* __restrict__ D, const float* __restrict__ Q, const float* __restrict__ PM,
    const float* __restrict__ W1, const float* __restrict__ b1, const float* __restrict__ W2)
{
    __shared__ __align__(16) unsigned sA[2 * 128 * PA];
    __shared__ __align__(16) unsigned sB[2 * 16 * PB];
    __shared__ float sRed[2][128];
    const int m0 = blockIdx.x * 128, n0 = blockIdx.y * 128;
    const int tid = threadIdx.x, lane = tid & 31, wid = tid >> 5, wm = wid & 3, wn = wid >> 2;
    float c[2][8][4];
#pragma unroll
    for (int i = 0; i < 2; i++)
#pragma unroll
        for (int j = 0; j < 8; j++)
#pragma unroll
            for (int k = 0; k < 4; k++) c[i][j][k] = 0.f;
    const int am = tid >> 1, ak = (tid & 1) * 8, bk = tid >> 4;
    float ra[8], rb[8];
    auto loadAB = [&](int k0) {
        const int qd = k0 >> 10, kk = (k0 & 1023) + ak;
        const int r = m0 + am, b = r >> 8;
        const float4* dp = (const float4*)(D + (size_t)r * Hsz + kk);
        const float4* op = (const float4*)((((qd & 1) == 0) ? Q : PM) + (size_t)b * Hsz + kk);
        float4 d0 = dp[0], d1 = dp[1], o0 = op[0], o1 = op[1];
        if (qd < 2) {
            ra[0] = d0.x * o0.x; ra[1] = d0.y * o0.y; ra[2] = d0.z * o0.z; ra[3] = d0.w * o0.w;
            ra[4] = d1.x * o1.x; ra[5] = d1.y * o1.y; ra[6] = d1.z * o1.z; ra[7] = d1.w * o1.w;
        } else {
            ra[0] = fabsf(d0.x - o0.x); ra[1] = fabsf(d0.y - o0.y); ra[2] = fabsf(d0.z - o0.z); ra[3] = fabsf(d0.w - o0.w);
            ra[4] = fabsf(d1.x - o1.x); ra[5] = fabsf(d1.y - o1.y); ra[6] = fabsf(d1.z - o1.z); ra[7] = fabsf(d1.w - o1.w);
        }
        const float4* wp = (const float4*)(W1 + (size_t)(k0 + bk) * Hsz + n0 + (tid & 15) * 8);
        float4 w0 = wp[0], w1 = wp[1];
        rb[0] = w0.x; rb[1] = w0.y; rb[2] = w0.z; rb[3] = w0.w;
        rb[4] = w1.x; rb[5] = w1.y; rb[6] = w1.z; rb[7] = w1.w;
    };
    auto storeAB = [&](int bsel) {
        unsigned* pA = sA + bsel * 128 * PA;
        unsigned* pB = sB + bsel * 16 * PB;
#pragma unroll
        for (int i = 0; i < 8; i++) pA[am * PA + ak + i] = f2tf(ra[i]);
#pragma unroll
        for (int i = 0; i < 8; i++) pB[bk * PB + i * 16 + (tid & 15)] = f2tf(rb[i]);
    };
    loadAB(0); storeAB(0); __syncthreads();
    int cur = 0;
    for (int k0 = 0; k0 < 4096; k0 += 16) {
        const bool more = (k0 + 16) < 4096;
        if (more) loadAB(k0 + 16);
        tile_mma(sA + cur * 128 * PA, sB + cur * 16 * PB, c, lane, wm, wn);
        if (more) storeAB(cur ^ 1);
        __syncthreads();
        cur ^= 1;
    }
#pragma unroll
    for (int mt = 0; mt < 2; mt++) {
        float s0 = 0.f, s1 = 0.f;
#pragma unroll
        for (int nt = 0; nt < 8; nt++) {
            int nc = n0 + wn * 64 + nt * 8 + (lane & 3) * 2;
            float bb0 = b1[nc], bb1 = b1[nc + 1];
            float w0 = W2[nc], w1 = W2[nc + 1];
            s0 += tanhf(c[mt][nt][0] + bb0) * w0 + tanhf(c[mt][nt][1] + bb1) * w1;
            s1 += tanhf(c[mt][nt][2] + bb0) * w0 + tanhf(c[mt][nt][3] + bb1) * w1;
        }
        s0 += __shfl_xor_sync(0xffffffffu, s0, 1); s0 += __shfl_xor_sync(0xffffffffu, s0, 2);
        s1 += __shfl_xor_sync(0xffffffffu, s1, 1); s1 += __shfl_xor_sync(0xffffffffu, s1, 2);
        if ((lane & 3) == 0) {
            int rl = wm * 32 + mt * 16 + (lane >> 2);
            sRed[wn][rl] = s0; sRed[wn][rl + 8] = s1;
        }
    }
    __syncthreads();
    if (tid < 128) g_Zp[blockIdx.y * BS + m0 + tid] = sRed[0][tid] + sRed[1][tid];
}

__global__ void __launch_bounds__(256) softmax_kernel() {
    __shared__ float red[256];
    const int b = blockIdx.x, s = threadIdx.x;
    float v = 0.f;
#pragma unroll
    for (int p = 0; p < 8; p++) v += g_Zp[p * BS + b * Ssz + s];
    red[s] = v; __syncthreads();
    for (int o = 128; o > 0; o >>= 1) { if (s < o) red[s] = fmaxf(red[s], red[s + o]); __syncthreads(); }
    float mx = red[0]; __syncthreads();
    float e = expf(v - mx);
    red[s] = e; __syncthreads();
    for (int o = 128; o > 0; o >>= 1) { if (s < o) red[s] += red[s + o]; __syncthreads(); }
    g_G[b * Ssz + s] = e / red[0];
}

// ---------------- Dr|Dw ----------------
__global__ void __launch_bounds__(256) drw_kernel(
    const float* __restrict__ D, const float* __restrict__ Wr, const float* __restrict__ br,
    const float* __restrict__ Wx, const float* __restrict__ bx)
{
    __shared__ __align__(16) unsigned sA[2 * 128 * PA];
    __shared__ __align__(16) unsigned sB[2 * 16 * PB];
    const int m0 = blockIdx.x * 128, n0g = blockIdx.y * 128;
    const float* W = (n0g < 1024) ? Wr : Wx;
    const float* bias = (n0g < 1024) ? br : bx;
    const int n0 = n0g & 1023;
    const int tid = threadIdx.x, lane = tid & 31, wid = tid >> 5, wm = wid & 3, wn = wid >> 2;
    float c[2][8][4];
#pragma unroll
    for (int i = 0; i < 2; i++)
#pragma unroll
        for (int j = 0; j < 8; j++)
#pragma unroll
            for (int k = 0; k < 4; k++) c[i][j][k] = 0.f;
    const int am = tid >> 1, ak = (tid & 1) * 8, bk = tid >> 4;
    float ra[8], rb[8];
    auto loadAB = [&](int k0) {
        const float4* dp = (const float4*)(D + (size_t)(m0 + am) * Hsz + k0 + ak);
        float4 d0 = dp[0], d1 = dp[1];
        ra[0] = d0.x; ra[1] = d0.y; ra[2] = d0.z; ra[3] = d0.w;
        ra[4] = d1.x; ra[5] = d1.y; ra[6] = d1.z; ra[7] = d1.w;
        const float4* wp = (const float4*)(W + (size_t)(k0 + bk) * Hsz + n0 + (tid & 15) * 8);
        float4 w0 = wp[0], w1 = wp[1];
        rb[0] = w0.x; rb[1] = w0.y; rb[2] = w0.z; rb[3] = w0.w;
        rb[4] = w1.x; rb[5] = w1.y; rb[6] = w1.z; rb[7] = w1.w;
    };
    auto storeAB = [&](int bsel) {
        unsigned* pA = sA + bsel * 128 * PA;
        unsigned* pB = sB + bsel * 16 * PB;
#pragma unroll
        for (int i = 0; i < 8; i++) pA[am * PA + ak + i] = f2tf(ra[i]);
#pragma unroll
        for (int i = 0; i < 8; i++) pB[bk * PB + i * 16 + (tid & 15)] = f2tf(rb[i]);
    };
    loadAB(0); storeAB(0); __syncthreads();
    int cur = 0;
    for (int k0 = 0; k0 < 1024; k0 += 16) {
        const bool more = (k0 + 16) < 1024;
        if (more) loadAB(k0 + 16);
        tile_mma(sA + cur * 128 * PA, sB + cur * 16 * PB, c, lane, wm, wn);
        if (more) storeAB(cur ^ 1);
        __syncthreads();
        cur ^= 1;
    }
#pragma unroll
    for (int mt = 0; mt < 2; mt++)
#pragma unroll
        for (int nt = 0; nt < 8; nt++) {
            int nl = wn * 64 + nt * 8 + (lane & 3) * 2;
            int r0 = m0 + wm * 32 + mt * 16 + (lane >> 2);
            float bb0 = bias[n0 + nl], bb1 = bias[n0 + nl + 1];
            *(float2*)&g_Drw[(size_t)r0 * 2048 + n0g + nl] = make_float2(c[mt][nt][0] + bb0, c[mt][nt][1] + bb1);
            *(float2*)&g_Drw[(size_t)(r0 + 8) * 2048 + n0g + nl] = make_float2(c[mt][nt][2] + bb0, c[mt][nt][3] + bb1);
        }
}

// ---------------- persistent scan: fp16 h, 16KB chunks, 2-ring bulk pipeline ----------------
// words: ring 2*4096 | sW 32*512 | sP 64*33 | bias 32 | mbar 4
#define R_RING 0
#define R_SW   8192
#define R_SP   (R_SW + 16384)
#define R_BIAS (R_SP + 64 * 33)
#define R_MB   (R_BIAS + 32)
#define SCAN_WORDS (R_MB + 4)
#define SCAN_SMEM  (SCAN_WORDS * 4 + 1024)

__device__ __forceinline__ void gbar() {
    __threadfence();
    __syncthreads();
    if (threadIdx.x == 0) {
        unsigned gen = g_bar_gen;
        if (atomicAdd((unsigned*)&g_bar_arrive, 1u) == NCTA - 1) {
            g_bar_arrive = 0;
            __threadfence();
            g_bar_gen = gen + 1;
        } else {
            while (g_bar_gen == gen) __nanosleep(32);
            __threadfence();
        }
    }
    __syncthreads();
}

__global__ void __launch_bounds__(256, 1) scan_kernel(
    const float* __restrict__ Ur, const float* __restrict__ U,
    const float* __restrict__ bur, const float* __restrict__ bu,
    float* __restrict__ hs)
{
    extern __shared__ __align__(16) unsigned dynraw[];
    unsigned* dyn = (unsigned*)(((uintptr_t)dynraw + 1023) & ~(uintptr_t)1023);
    unsigned* ring = dyn + R_RING;
    unsigned* sW = dyn + R_SW;
    float* sP = (float*)(dyn + R_SP);
    float* sBias = (float*)(dyn + R_BIAS);
    unsigned mb0 = (unsigned)__cvta_generic_to_shared(dyn + R_MB);
    unsigned ring_u32 = (unsigned)__cvta_generic_to_shared(ring);

    const int j = blockIdx.x, tid = threadIdx.x, lane = tid & 31, wid = tid >> 5;
    const int wm = wid & 3, wn = wid >> 2, q = lane >> 2, la3 = lane & 3;

    // weights fp16: sW[n][k-pair] with XOR swizzle by (n&7)<<2
    for (int idx = tid; idx < 16 * 1024; idx += 256) {
        int n = idx & 31, k2 = idx >> 5;
        int k = k2 * 2;
        float v0, v1;
        if (n < 16) { v0 = Ur[(size_t)k * Hsz + j * 16 + n];       v1 = Ur[(size_t)(k + 1) * Hsz + j * 16 + n]; }
        else        { v0 = U[(size_t)k * Hsz + j * 16 + (n - 16)]; v1 = U[(size_t)(k + 1) * Hsz + j * 16 + (n - 16)]; }
        __half2 p = __floats2half2_rn(v0, v1);
        sW[n * SWROW + (k2 ^ ((n & 7) << 2))] = *(unsigned*)&p;
    }
    if (tid < 16)      sBias[tid] = bur[j * 16 + tid];
    else if (tid < 32) sBias[tid] = bu[j * 16 + tid - 16];
    if (tid == 0) {
        asm volatile("mbarrier.init.shared.b64 [%0], 1;" :: "r"(mb0) : "memory");
        asm volatile("mbarrier.init.shared.b64 [%0], 1;" :: "r"(mb0 + 8) : "memory");
        asm volatile("fence.proxy.async.shared::cta;" ::: "memory");
    }
    __syncthreads();

    const int b_e = tid >> 2, c4 = (tid & 3) * 4;
    const int wsw = (b_e & 7) << 2;                       // writer swizzle
    const int w0base = (j & 7) * 8 + (tid & 3) * 2;       // writer k-word
    const int asw = q << 2;                                // A reader swizzle (row&7 == q)
    float hh[4] = {0.f, 0.f, 0.f, 0.f};
    int ph[2] = {0, 0};

    for (int t = 0; t < Ssz; t++) {
        const unsigned* hsrc = (const unsigned*)g_h2[(t & 1) ^ 1];
        if (tid == 0) {
            asm volatile("mbarrier.arrive.expect_tx.shared.b64 _, [%0], 16384;" :: "r"(mb0) : "memory");
            asm volatile("cp.async.bulk.shared::cta.global.mbarrier::complete_tx::bytes [%0], [%1], 16384, [%2];"
                         :: "r"(ring_u32), "l"(hsrc), "r"(mb0) : "memory");
        }
        const size_t rd = (size_t)b_e * Ssz + t;
        float4 dr4 = __ldcg((const float4*)(g_Drw + rd * 2048 + j * 16 + c4));
        float4 dw4 = __ldcg((const float4*)(g_Drw + rd * 2048 + 1024 + j * 16 + c4));
        float gt = __ldcg(g_G + rd);

        float acc[2][4] = {{0.f, 0.f, 0.f, 0.f}, {0.f, 0.f, 0.f, 0.f}};
        for (int cch = 0; cch < 8; cch++) {
            if (cch < 7 && tid == 0) {
                int b2 = (cch + 1) & 1;
                asm volatile("mbarrier.arrive.expect_tx.shared.b64 _, [%0], 16384;" :: "r"(mb0 + b2 * 8) : "memory");
                asm volatile("cp.async.bulk.shared::cta.global.mbarrier::complete_tx::bytes [%0], [%1], 16384, [%2];"
                             :: "r"(ring_u32 + b2 * 16384), "l"(hsrc + (cch + 1) * 4096), "r"(mb0 + b2 * 8) : "memory");
            }
            int buf = cch & 1;
            {
                unsigned mba = mb0 + buf * 8;
                unsigned par = (unsigned)ph[buf];
                asm volatile(
                    "{\n\t.reg .pred P1;\n\t"
                    "WL_%=:\n\t"
                    "mbarrier.try_wait.parity.acquire.cta.shared::cta.b64 P1, [%0], %1, 0x989680;\n\t"
                    "@P1 bra.uni WD_%=;\n\t"
                    "bra.uni WL_%=;\n\t"
                    "WD_%=:\n\t}"
                    :: "r"(mba), "r"(par) : "memory");
                ph[buf] ^= 1;
            }
            const unsigned* cb = ring + buf * 4096;
            const int rA0 = (wm * 16 + q) * 64, rA1 = rA0 + 8 * 64;
#pragma unroll
            for (int ks = 0; ks < 8; ks++) {
                int kw = ks * 8;
                unsigned a[4];
                a[0] = cb[rA0 + ((kw + la3) ^ asw)];
                a[1] = cb[rA1 + ((kw + la3) ^ asw)];
                a[2] = cb[rA0 + ((kw + la3 + 4) ^ asw)];
                a[3] = cb[rA1 + ((kw + la3 + 4) ^ asw)];
                int kp = cch * 64 + kw;    // k-pair base (global k /2)
                unsigned bf0[2], bf1[2];
                int rB0 = (wn * 16 + q) * SWROW, rB1 = rB0 + 8 * SWROW;
                bf0[0] = sW[rB0 + ((kp + la3) ^ asw)];
                bf0[1] = sW[rB0 + ((kp + la3 + 4) ^ asw)];
                bf1[0] = sW[rB1 + ((kp + la3) ^ asw)];
                bf1[1] = sW[rB1 + ((kp + la3 + 4) ^ asw)];
                mmah(acc[0], a, bf0);
                mmah(acc[1], a, bf1);
            }
            __syncthreads();
        }
        {
            int r = wm * 16 + q;
            int c0 = wn * 16 + 2 * la3, c1 = c0 + 8;
            sP[r * 33 + c0] = acc[0][0]; sP[r * 33 + c0 + 1] = acc[0][1];
            sP[(r + 8) * 33 + c0] = acc[0][2]; sP[(r + 8) * 33 + c0 + 1] = acc[0][3];
            sP[r * 33 + c1] = acc[1][0]; sP[r * 33 + c1 + 1] = acc[1][1];
            sP[(r + 8) * 33 + c1] = acc[1][2]; sP[(r + 8) * 33 + c1 + 1] = acc[1][3];
        }
        __syncthreads();
        {
            float dr[4] = {dr4.x, dr4.y, dr4.z, dr4.w};
            float dw[4] = {dw4.x, dw4.y, dw4.z, dw4.w};
            float4 ho; float* hop = &ho.x;
#pragma unroll
            for (int i = 0; i < 4; i++) {
                int cc = c4 + i;
                float r = 1.f / (1.f + expf(-(dr[i] + sP[b_e * 33 + cc] + sBias[cc])));
                float ht = tanhf(dw[i] + r * (sP[b_e * 33 + 16 + cc] + sBias[16 + cc]));
                hh[i] = gt * ht + (1.f - gt) * hh[i];
                hop[i] = hh[i];
            }
            *(float4*)&hs[rd * Hsz + j * 16 + c4] = ho;
            __half2 p01 = __floats2half2_rn(hh[0], hh[1]);
            __half2 p23 = __floats2half2_rn(hh[2], hh[3]);
            uint2 pk = make_uint2(*(unsigned*)&p01, *(unsigned*)&p23);
            unsigned* dstT = (unsigned*)g_h2[t & 1][j >> 3];
            *(uint2*)&dstT[b_e * 64 + (w0base ^ wsw)] = pk;
        }
        gbar();
    }
}

// ---------------- next_mem ----------------
__global__ void __launch_bounds__(256) nextmem_kernel(
    const float* __restrict__ PM, const float* __restrict__ Q,
    const float* __restrict__ Wm, const float* __restrict__ bm,
    float* __restrict__ out, const float* __restrict__ hs)
{
    __shared__ float sW6[64 * 16];
    __shared__ float sC[64 * 65];
    const int j = blockIdx.x, tid = threadIdx.x;
    const int n = tid & 15, brow = tid >> 4;
    float acc[4] = {0.f, 0.f, 0.f, 0.f};
    for (int k0 = 0; k0 < 3072; k0 += 64) {
        sW6[tid] = Wm[(size_t)(k0 + (tid >> 4)) * Hsz + j * 16 + (tid & 15)];
        sW6[tid + 256] = Wm[(size_t)(k0 + 16 + (tid >> 4)) * Hsz + j * 16 + (tid & 15)];
        sW6[tid + 512] = Wm[(size_t)(k0 + 32 + (tid >> 4)) * Hsz + j * 16 + (tid & 15)];
        sW6[tid + 768] = Wm[(size_t)(k0 + 48 + (tid >> 4)) * Hsz + j * 16 + (tid & 15)];
#pragma unroll
        for (int it = 0; it < 16; it++) {
            int idx = tid + 256 * it;
            int b = idx >> 6, kk = idx & 63, k = k0 + kk;
            float v = (k < 1024) ? PM[b * Hsz + k]
                    : (k < 2048) ? hs[((size_t)b * Ssz + 255) * Hsz + k - 1024]
                                 : Q[b * Hsz + k - 2048];
            sC[b * 65 + kk] = v;
        }
        __syncthreads();
#pragma unroll 8
        for (int kk = 0; kk < 64; kk++) {
            float w = sW6[kk * 16 + n];
            acc[0] += sC[brow * 65 + kk] * w;
            acc[1] += sC[(brow + 16) * 65 + kk] * w;
            acc[2] += sC[(brow + 32) * 65 + kk] * w;
            acc[3] += sC[(brow + 48) * 65 + kk] * w;
        }
        __syncthreads();
    }
    float bb = bm[j * 16 + n];
    out[(size_t)brow * Hsz + j * 16 + n]        = fmaxf(acc[0] + bb, 0.f);
    out[(size_t)(brow + 16) * Hsz + j * 16 + n] = fmaxf(acc[1] + bb, 0.f);
    out[(size_t)(brow + 32) * Hsz + j * 16 + n] = fmaxf(acc[2] + bb, 0.f);
    out[(size_t)(brow + 48) * Hsz + j * 16 + n] = fmaxf(acc[3] + bb, 0.f);
}

extern "C" void kernel_launch(void* const* d_in, const int* in_sizes, int n_in,
                              void* d_out, int out_size) {
    const float* D   = (const float*)d_in[0];
    const float* Q   = (const float*)d_in[1];
    const float* PM  = (const float*)d_in[2];
    const float* Wr  = (const float*)d_in[3];
    const float* br  = (const float*)d_in[4];
    const float* Ur  = (const float*)d_in[5];
    const float* bur = (const float*)d_in[6];
    const float* Wx  = (const float*)d_in[7];
    const float* bx  = (const float*)d_in[8];
    const float* U   = (const float*)d_in[9];
    const float* bu  = (const float*)d_in[10];
    const float* W1  = (const float*)d_in[11];
    const float* b1  = (const float*)d_in[12];
    const float* W2  = (const float*)d_in[13];
    const float* Wm  = (const float*)d_in[15];
    const float* bm  = (const float*)d_in[16];
    float* out = (float*)d_out;

    static int attr_done = 0;
    if (!attr_done) {
        cudaFuncSetAttribute(scan_kernel, cudaFuncAttributeMaxDynamicSharedMemorySize, SCAN_SMEM);
        attr_done = 1;
    }

    init_kernel<<<512, 256>>>();
    gate_kernel<<<dim3(128, 8), 256>>>(D, Q, PM, W1, b1, W2);
    softmax_kernel<<<64, 256>>>();
    drw_kernel<<<dim3(128, 16), 256>>>(D, Wr, br, Wx, bx);
    scan_kernel<<<NCTA, 256, SCAN_SMEM>>>(Ur, U, bur, bu, out + Bsz * Hsz);
    nextmem_kernel<<<64, 256>>>(PM, Q, Wm, bm, out, out + Bsz * Hsz);
}

// round 13
// speedup vs baseline: 1.4114x; 1.0745x over previous
#include <cuda_runtime.h>
#include <cuda_fp16.h>
#include <math.h>
#include <stdint.h>

#define Bsz 64
#define Ssz 256
#define Hsz 1024
#define BS  16384
#define NCTA 128

__device__ __align__(16) float g_Drw[(size_t)BS * 2048];
__device__ __align__(16) float g_Zp[8 * BS];
__device__ __align__(16) float g_G[BS];
__device__ __align__(256) unsigned g_hf[2][2][4][4096];  // [buf][bhalf][chunk][b*128 + swizzled k-word]
__device__ volatile unsigned g_bar_arrive;
__device__ volatile unsigned g_bar_gen;

#define PA 20
#define PB 132
#define SWROW 512

__device__ __forceinline__ unsigned f2tf(float x) {
    unsigned r; asm("cvt.rna.tf32.f32 %0, %1;" : "=r"(r) : "f"(x)); return r;
}
__device__ __forceinline__ void mma8(float* c, const unsigned* a, const unsigned* b) {
    asm volatile("mma.sync.aligned.m16n8k8.row.col.f32.tf32.tf32.f32 "
                 "{%0,%1,%2,%3},{%4,%5,%6,%7},{%8,%9},{%0,%1,%2,%3};"
                 : "+f"(c[0]), "+f"(c[1]), "+f"(c[2]), "+f"(c[3])
                 : "r"(a[0]), "r"(a[1]), "r"(a[2]), "r"(a[3]), "r"(b[0]), "r"(b[1]));
}
__device__ __forceinline__ void mmah(float* c, const unsigned* a, const unsigned* b) {
    asm volatile("mma.sync.aligned.m16n8k16.row.col.f32.f16.f16.f32 "
                 "{%0,%1,%2,%3},{%4,%5,%6,%7},{%8,%9},{%0,%1,%2,%3};"
                 : "+f"(c[0]), "+f"(c[1]), "+f"(c[2]), "+f"(c[3])
                 : "r"(a[0]), "r"(a[1]), "r"(a[2]), "r"(a[3]), "r"(b[0]), "r"(b[1]));
}

__device__ __forceinline__ void tile_mma(const unsigned* sA, const unsigned* sB,
                                         float c[2][8][4], int lane, int wm, int wn) {
    const int q = lane >> 2, la3 = lane & 3;
#pragma unroll
    for (int kk = 0; kk < 16; kk += 8) {
        unsigned a[2][4];
#pragma unroll
        for (int mt = 0; mt < 2; mt++) {
            int r = wm * 32 + mt * 16 + q, cc = kk + la3;
            a[mt][0] = sA[r * PA + cc];     a[mt][1] = sA[(r + 8) * PA + cc];
            a[mt][2] = sA[r * PA + cc + 4]; a[mt][3] = sA[(r + 8) * PA + cc + 4];
        }
        int kx = kk + la3, cb = q * 16 + wn * 8;
        uint4 b0 = *(const uint4*)&sB[kx * PB + cb];
        uint4 b1 = *(const uint4*)&sB[kx * PB + cb + 4];
        uint4 b2 = *(const uint4*)&sB[(kx + 4) * PB + cb];
        uint4 b3 = *(const uint4*)&sB[(kx + 4) * PB + cb + 4];
        unsigned bf[8][2] = {{b0.x,b2.x},{b0.y,b2.y},{b0.z,b2.z},{b0.w,b2.w},
                             {b1.x,b3.x},{b1.y,b3.y},{b1.z,b3.z},{b1.w,b3.w}};
#pragma unroll
        for (int mt = 0; mt < 2; mt++)
#pragma unroll
            for (int nt = 0; nt < 8; nt++) mma8(c[mt][nt], a[mt], bf[nt]);
    }
}

__global__ void init_kernel() {
    int i = blockIdx.x * blockDim.x + threadIdx.x;
    if (i == 0) { g_bar_arrive = 0; g_bar_gen = 0; }
    if (i < 2 * 2 * 4 * 4096) ((unsigned*)g_hf)[i] = 0u;
}

// ---------------- gate GEMM ----------------
__global__ void __launch_bounds__(256) gate_kernel(
    const float* __restrict__ D, const float* __restrict__ Q, const float* __restrict__ PM,
    const float* __restrict__ W1, const float* __restrict__ b1, const float* __restrict__ W2)
{
    __shared__ __align__(16) unsigned sA[2 * 128 * PA];
    __shared__ __align__(16) unsigned sB[2 * 16 * PB];
    __shared__ float sRed[2][128];
    const int m0 = blockIdx.x * 128, n0 = blockIdx.y * 128;
    const int tid = threadIdx.x, lane = tid & 31, wid = tid >> 5, wm = wid & 3, wn = wid >> 2;
    float c[2][8][4];
#pragma unroll
    for (int i = 0; i < 2; i++)
#pragma unroll
        for (int j = 0; j < 8; j++)
#pragma unroll
            for (int k = 0; k < 4; k++) c[i][j][k] = 0.f;
    const int am = tid >> 1, ak = (tid & 1) * 8, bk = tid >> 4;
    float ra[8], rb[8];
    auto loadAB = [&](int k0) {
        const int qd = k0 >> 10, kk = (k0 & 1023) + ak;
        const int r = m0 + am, b = r >> 8;
        const float4* dp = (const float4*)(D + (size_t)r * Hsz + kk);
        const float4* op = (const float4*)((((qd & 1) == 0) ? Q : PM) + (size_t)b * Hsz + kk);
        float4 d0 = dp[0], d1 = dp[1], o0 = op[0], o1 = op[1];
        if (qd < 2) {
            ra[0] = d0.x * o0.x; ra[1] = d0.y * o0.y; ra[2] = d0.z * o0.z; ra[3] = d0.w * o0.w;
            ra[4] = d1.x * o1.x; ra[5] = d1.y * o1.y; ra[6] = d1.z * o1.z; ra[7] = d1.w * o1.w;
        } else {
            ra[0] = fabsf(d0.x - o0.x); ra[1] = fabsf(d0.y - o0.y); ra[2] = fabsf(d0.z - o0.z); ra[3] = fabsf(d0.w - o0.w);
            ra[4] = fabsf(d1.x - o1.x); ra[5] = fabsf(d1.y - o1.y); ra[6] = fabsf(d1.z - o1.z); ra[7] = fabsf(d1.w - o1.w);
        }
        const float4* wp = (const float4*)(W1 + (size_t)(k0 + bk) * Hsz + n0 + (tid & 15) * 8);
        float4 w0 = wp[0], w1 = wp[1];
        rb[0] = w0.x; rb[1] = w0.y; rb[2] = w0.z; rb[3] = w0.w;
        rb[4] = w1.x; rb[5] = w1.y; rb[6] = w1.z; rb[7] = w1.w;
    };
    auto storeAB = [&](int bsel) {
        unsigned* pA = sA + bsel * 128 * PA;
        unsigned* pB = sB + bsel * 16 * PB;
#pragma unroll
        for (int i = 0; i < 8; i++) pA[am * PA + ak + i] = f2tf(ra[i]);
#pragma unroll
        for (int i = 0; i < 8; i++) pB[bk * PB + i * 16 + (tid & 15)] = f2tf(rb[i]);
    };
    loadAB(0); storeAB(0); __syncthreads();
    int cur = 0;
    for (int k0 = 0; k0 < 4096; k0 += 16) {
        const bool more = (k0 + 16) < 4096;
        if (more) loadAB(k0 + 16);
        tile_mma(sA + cur * 128 * PA, sB + cur * 16 * PB, c, lane, wm, wn);
        if (more) storeAB(cur ^ 1);
        __syncthreads();
        cur ^= 1;
    }
#pragma unroll
    for (int mt = 0; mt < 2; mt++) {
        float s0 = 0.f, s1 = 0.f;
#pragma unroll
        for (int nt = 0; nt < 8; nt++) {
            int nc = n0 + wn * 64 + nt * 8 + (lane & 3) * 2;
            float bb0 = b1[nc], bb1 = b1[nc + 1];
            float w0 = W2[nc], w1 = W2[nc + 1];
            s0 += tanhf(c[mt][nt][0] + bb0) * w0 + tanhf(c[mt][nt][1] + bb1) * w1;
            s1 += tanhf(c[mt][nt][2] + bb0) * w0 + tanhf(c[mt][nt][3] + bb1) * w1;
        }
        s0 += __shfl_xor_sync(0xffffffffu, s0, 1); s0 += __shfl_xor_sync(0xffffffffu, s0, 2);
        s1 += __shfl_xor_sync(0xffffffffu, s1, 1); s1 += __shfl_xor_sync(0xffffffffu, s1, 2);
        if ((lane & 3) == 0) {
            int rl = wm * 32 + mt * 16 + (lane >> 2);
            sRed[wn][rl] = s0; sRed[wn][rl + 8] = s1;
        }
    }
    __syncthreads();
    if (tid < 128) g_Zp[blockIdx.y * BS + m0 + tid] = sRed[0][tid] + sRed[1][tid];
}

__global__ void __launch_bounds__(256) softmax_kernel() {
    __shared__ float red[256];
    const int b = blockIdx.x, s = threadIdx.x;
    float v = 0.f;
#pragma unroll
    for (int p = 0; p < 8; p++) v += g_Zp[p * BS + b * Ssz + s];
    red[s] = v; __syncthreads();
    for (int o = 128; o > 0; o >>= 1) { if (s < o) red[s] = fmaxf(red[s], red[s + o]); __syncthreads(); }
    float mx = red[0]; __syncthreads();
    float e = expf(v - mx);
    red[s] = e; __syncthreads();
    for (int o = 128; o > 0; o >>= 1) { if (s < o) red[s] += red[s + o]; __syncthreads(); }
    g_G[b * Ssz + s] = e / red[0];
}

// ---------------- Dr|Dw ----------------
__global__ void __launch_bounds__(256) drw_kernel(
    const float* __restrict__ D, const float* __restrict__ Wr, const float* __restrict__ br,
    const float* __restrict__ Wx, const float* __restrict__ bx)
{
    __shared__ __align__(16) unsigned sA[2 * 128 * PA];
    __shared__ __align__(16) unsigned sB[2 * 16 * PB];
    const int m0 = blockIdx.x * 128, n0g = blockIdx.y * 128;
    const float* W = (n0g < 1024) ? Wr : Wx;
    const float* bias = (n0g < 1024) ? br : bx;
    const int n0 = n0g & 1023;
    const int tid = threadIdx.x, lane = tid & 31, wid = tid >> 5, wm = wid & 3, wn = wid >> 2;
    float c[2][8][4];
#pragma unroll
    for (int i = 0; i < 2; i++)
#pragma unroll
        for (int j = 0; j < 8; j++)
#pragma unroll
            for (int k = 0; k < 4; k++) c[i][j][k] = 0.f;
    const int am = tid >> 1, ak = (tid & 1) * 8, bk = tid >> 4;
    float ra[8], rb[8];
    auto loadAB = [&](int k0) {
        const float4* dp = (const float4*)(D + (size_t)(m0 + am) * Hsz + k0 + ak);
        float4 d0 = dp[0], d1 = dp[1];
        ra[0] = d0.x; ra[1] = d0.y; ra[2] = d0.z; ra[3] = d0.w;
        ra[4] = d1.x; ra[5] = d1.y; ra[6] = d1.z; ra[7] = d1.w;
        const float4* wp = (const float4*)(W + (size_t)(k0 + bk) * Hsz + n0 + (tid & 15) * 8);
        float4 w0 = wp[0], w1 = wp[1];
        rb[0] = w0.x; rb[1] = w0.y; rb[2] = w0.z; rb[3] = w0.w;
        rb[4] = w1.x; rb[5] = w1.y; rb[6] = w1.z; rb[7] = w1.w;
    };
    auto storeAB = [&](int bsel) {
        unsigned* pA = sA + bsel * 128 * PA;
        unsigned* pB = sB + bsel * 16 * PB;
#pragma unroll
        for (int i = 0; i < 8; i++) pA[am * PA + ak + i] = f2tf(ra[i]);
#pragma unroll
        for (int i = 0; i < 8; i++) pB[bk * PB + i * 16 + (tid & 15)] = f2tf(rb[i]);
    };
    loadAB(0); storeAB(0); __syncthreads();
    int cur = 0;
    for (int k0 = 0; k0 < 1024; k0 += 16) {
        const bool more = (k0 + 16) < 1024;
        if (more) loadAB(k0 + 16);
        tile_mma(sA + cur * 128 * PA, sB + cur * 16 * PB, c, lane, wm, wn);
        if (more) storeAB(cur ^ 1);
        __syncthreads();
        cur ^= 1;
    }
#pragma unroll
    for (int mt = 0; mt < 2; mt++)
#pragma unroll
        for (int nt = 0; nt < 8; nt++) {
            int nl = wn * 64 + nt * 8 + (lane & 3) * 2;
            int r0 = m0 + wm * 32 + mt * 16 + (lane >> 2);
            float bb0 = bias[n0 + nl], bb1 = bias[n0 + nl + 1];
            *(float2*)&g_Drw[(size_t)r0 * 2048 + n0g + nl] = make_float2(c[mt][nt][0] + bb0, c[mt][nt][1] + bb1);
            *(float2*)&g_Drw[(size_t)(r0 + 8) * 2048 + n0g + nl] = make_float2(c[mt][nt][2] + bb0, c[mt][nt][3] + bb1);
        }
}

// ---------------- persistent scan: fp16 h, batch-split (128 CTAs, M=32), 4x16KB chunks ----------------
// words: ring 2*4096 | sW 32*512 | sP 32*33 | bias 32 | mbar 4
#define R_RING 0
#define R_SW   8192
#define R_SP   (R_SW + 16384)
#define R_BIAS (R_SP + 32 * 33)
#define R_MB   (R_BIAS + 32)
#define SCAN_WORDS (R_MB + 4)
#define SCAN_SMEM  (SCAN_WORDS * 4 + 1024)

__device__ __forceinline__ void gbar() {
    __threadfence();
    __syncthreads();
    if (threadIdx.x == 0) {
        unsigned gen = g_bar_gen;
        if (atomicAdd((unsigned*)&g_bar_arrive, 1u) == NCTA - 1) {
            g_bar_arrive = 0;
            __threadfence();
            g_bar_gen = gen + 1;
        } else {
            while (g_bar_gen == gen) __nanosleep(32);
            __threadfence();
        }
    }
    __syncthreads();
}

__global__ void __launch_bounds__(256, 1) scan_kernel(
    const float* __restrict__ Ur, const float* __restrict__ U,
    const float* __restrict__ bur, const float* __restrict__ bu,
    float* __restrict__ hs)
{
    extern __shared__ __align__(16) unsigned dynraw[];
    unsigned* dyn = (unsigned*)(((uintptr_t)dynraw + 1023) & ~(uintptr_t)1023);
    unsigned* ring = dyn + R_RING;
    unsigned* sW = dyn + R_SW;
    float* sP = (float*)(dyn + R_SP);
    float* sBias = (float*)(dyn + R_BIAS);
    unsigned mb0 = (unsigned)__cvta_generic_to_shared(dyn + R_MB);
    unsigned ring_u32 = (unsigned)__cvta_generic_to_shared(ring);

    const int jc = blockIdx.x & 63;          // column group (16 cols)
    const int bh = blockIdx.x >> 6;          // batch half
    const int tid = threadIdx.x, lane = tid & 31, wid = tid >> 5;
    const int wm = wid & 1, wn = wid >> 1, q = lane >> 2, la3 = lane & 3;

    // weights fp16: sW[n][k-pair] with XOR swizzle by (n&7)<<2  (same as R12)
    for (int idx = tid; idx < 16 * 1024; idx += 256) {
        int n = idx & 31, k2 = idx >> 5;
        int k = k2 * 2;
        float v0, v1;
        if (n < 16) { v0 = Ur[(size_t)k * Hsz + jc * 16 + n];       v1 = Ur[(size_t)(k + 1) * Hsz + jc * 16 + n]; }
        else        { v0 = U[(size_t)k * Hsz + jc * 16 + (n - 16)]; v1 = U[(size_t)(k + 1) * Hsz + jc * 16 + (n - 16)]; }
        __half2 p = __floats2half2_rn(v0, v1);
        sW[n * SWROW + (k2 ^ ((n & 7) << 2))] = *(unsigned*)&p;
    }
    if (tid < 16)      sBias[tid] = bur[jc * 16 + tid];
    else if (tid < 32) sBias[tid] = bu[jc * 16 + tid - 16];
    if (tid == 0) {
        asm volatile("mbarrier.init.shared.b64 [%0], 1;" :: "r"(mb0) : "memory");
        asm volatile("mbarrier.init.shared.b64 [%0], 1;" :: "r"(mb0 + 8) : "memory");
        asm volatile("fence.proxy.async.shared::cta;" ::: "memory");
    }
    __syncthreads();

    // epilogue mapping: thread -> (batch bb, col pair cp)
    const int bb = tid >> 3, cp = (tid & 7) * 2;
    const int gb = bh * 32 + bb;                          // global batch
    const int kc_own = jc >> 4;                           // chunk containing our columns
    const int wword = (jc & 15) * 8 + (tid & 7);          // k-word within chunk row
    const int wsw = (bb & 7) << 2;
    const int asw = q << 2;
    float hh[2] = {0.f, 0.f};
    int ph[2] = {0, 0};

    for (int t = 0; t < Ssz; t++) {
        const unsigned* hsrc = (const unsigned*)g_hf[(t & 1) ^ 1][bh];
        if (tid == 0) {
            asm volatile("mbarrier.arrive.expect_tx.shared.b64 _, [%0], 16384;" :: "r"(mb0) : "memory");
            asm volatile("cp.async.bulk.shared::cta.global.mbarrier::complete_tx::bytes [%0], [%1], 16384, [%2];"
                         :: "r"(ring_u32), "l"(hsrc), "r"(mb0) : "memory");
        }
        const size_t rd = (size_t)gb * Ssz + t;
        float2 dr2 = __ldcg((const float2*)(g_Drw + rd * 2048 + jc * 16 + cp));
        float2 dw2 = __ldcg((const float2*)(g_Drw + rd * 2048 + 1024 + jc * 16 + cp));
        float gt = __ldcg(g_G + rd);

        float acc[4] = {0.f, 0.f, 0.f, 0.f};
        for (int cch = 0; cch < 4; cch++) {
            if (cch < 3 && tid == 0) {
                int b2 = (cch + 1) & 1;
                asm volatile("mbarrier.arrive.expect_tx.shared.b64 _, [%0], 16384;" :: "r"(mb0 + b2 * 8) : "memory");
                asm volatile("cp.async.bulk.shared::cta.global.mbarrier::complete_tx::bytes [%0], [%1], 16384, [%2];"
                             :: "r"(ring_u32 + b2 * 16384), "l"(hsrc + (cch + 1) * 4096), "r"(mb0 + b2 * 8) : "memory");
            }
            int buf = cch & 1;
            {
                unsigned mba = mb0 + buf * 8;
                unsigned par = (unsigned)ph[buf];
                asm volatile(
                    "{\n\t.reg .pred P1;\n\t"
                    "WL_%=:\n\t"
                    "mbarrier.try_wait.parity.acquire.cta.shared::cta.b64 P1, [%0], %1, 0x989680;\n\t"
                    "@P1 bra.uni WD_%=;\n\t"
                    "bra.uni WL_%=;\n\t"
                    "WD_%=:\n\t}"
                    :: "r"(mba), "r"(par) : "memory");
                ph[buf] ^= 1;
            }
            const unsigned* cb = ring + buf * 4096;
            const int rA0 = (wm * 16 + q) * 128, rA1 = rA0 + 8 * 128;
            const int rB = (wn * 8 + q) * SWROW;
#pragma unroll
            for (int ks = 0; ks < 16; ks++) {
                int kw = ks * 8;
                unsigned a[4];
                a[0] = cb[rA0 + ((kw + la3) ^ asw)];
                a[1] = cb[rA1 + ((kw + la3) ^ asw)];
                a[2] = cb[rA0 + ((kw + la3 + 4) ^ asw)];
                a[3] = cb[rA1 + ((kw + la3 + 4) ^ asw)];
                int kp = cch * 128 + kw;
                unsigned bf[2];
                bf[0] = sW[rB + ((kp + la3) ^ asw)];
                bf[1] = sW[rB + ((kp + la3 + 4) ^ asw)];
                mmah(acc, a, bf);
            }
            __syncthreads();
        }
        {
            int r = wm * 16 + q;
            int c0 = wn * 8 + 2 * la3;
            sP[r * 33 + c0] = acc[0]; sP[r * 33 + c0 + 1] = acc[1];
            sP[(r + 8) * 33 + c0] = acc[2]; sP[(r + 8) * 33 + c0 + 1] = acc[3];
        }
        __syncthreads();
        {
            float dr[2] = {dr2.x, dr2.y};
            float dw[2] = {dw2.x, dw2.y};
            float2 ho;
            float* hop = &ho.x;
#pragma unroll
            for (int i = 0; i < 2; i++) {
                int cc = cp + i;
                float r = 1.f / (1.f + expf(-(dr[i] + sP[bb * 33 + cc] + sBias[cc])));
                float ht = tanhf(dw[i] + r * (sP[bb * 33 + 16 + cc] + sBias[16 + cc]));
                hh[i] = gt * ht + (1.f - gt) * hh[i];
                hop[i] = hh[i];
            }
            *(float2*)&hs[rd * Hsz + jc * 16 + cp] = ho;
            __half2 p01 = __floats2half2_rn(hh[0], hh[1]);
            unsigned* dstT = (unsigned*)g_hf[t & 1][bh][kc_own];
            dstT[bb * 128 + (wword ^ wsw)] = *(unsigned*)&p01;
        }
        gbar();
    }
}

// ---------------- next_mem ----------------
__global__ void __launch_bounds__(256) nextmem_kernel(
    const float* __restrict__ PM, const float* __restrict__ Q,
    const float* __restrict__ Wm, const float* __restrict__ bm,
    float* __restrict__ out, const float* __restrict__ hs)
{
    __shared__ float sW6[64 * 16];
    __shared__ float sC[64 * 65];
    const int j = blockIdx.x, tid = threadIdx.x;
    const int n = tid & 15, brow = tid >> 4;
    float acc[4] = {0.f, 0.f, 0.f, 0.f};
    for (int k0 = 0; k0 < 3072; k0 += 64) {
        sW6[tid] = Wm[(size_t)(k0 + (tid >> 4)) * Hsz + j * 16 + (tid & 15)];
        sW6[tid + 256] = Wm[(size_t)(k0 + 16 + (tid >> 4)) * Hsz + j * 16 + (tid & 15)];
        sW6[tid + 512] = Wm[(size_t)(k0 + 32 + (tid >> 4)) * Hsz + j * 16 + (tid & 15)];
        sW6[tid + 768] = Wm[(size_t)(k0 + 48 + (tid >> 4)) * Hsz + j * 16 + (tid & 15)];
#pragma unroll
        for (int it = 0; it < 16; it++) {
            int idx = tid + 256 * it;
            int b = idx >> 6, kk = idx & 63, k = k0 + kk;
            float v = (k < 1024) ? PM[b * Hsz + k]
                    : (k < 2048) ? hs[((size_t)b * Ssz + 255) * Hsz + k - 1024]
                                 : Q[b * Hsz + k - 2048];
            sC[b * 65 + kk] = v;
        }
        __syncthreads();
#pragma unroll 8
        for (int kk = 0; kk < 64; kk++) {
            float w = sW6[kk * 16 + n];
            acc[0] += sC[brow * 65 + kk] * w;
            acc[1] += sC[(brow + 16) * 65 + kk] * w;
            acc[2] += sC[(brow + 32) * 65 + kk] * w;
            acc[3] += sC[(brow + 48) * 65 + kk] * w;
        }
        __syncthreads();
    }
    float bb = bm[j * 16 + n];
    out[(size_t)brow * Hsz + j * 16 + n]        = fmaxf(acc[0] + bb, 0.f);
    out[(size_t)(brow + 16) * Hsz + j * 16 + n] = fmaxf(acc[1] + bb, 0.f);
    out[(size_t)(brow + 32) * Hsz + j * 16 + n] = fmaxf(acc[2] + bb, 0.f);
    out[(size_t)(brow + 48) * Hsz + j * 16 + n] = fmaxf(acc[3] + bb, 0.f);
}

extern "C" void kernel_launch(void* const* d_in, const int* in_sizes, int n_in,
                              void* d_out, int out_size) {
    const float* D   = (const float*)d_in[0];
    const float* Q   = (const float*)d_in[1];
    const float* PM  = (const float*)d_in[2];
    const float* Wr  = (const float*)d_in[3];
    const float* br  = (const float*)d_in[4];
    const float* Ur  = (const float*)d_in[5];
    const float* bur = (const float*)d_in[6];
    const float* Wx  = (const float*)d_in[7];
    const float* bx  = (const float*)d_in[8];
    const float* U   = (const float*)d_in[9];
    const float* bu  = (const float*)d_in[10];
    const float* W1  = (const float*)d_in[11];
    const float* b1  = (const float*)d_in[12];
    const float* W2  = (const float*)d_in[13];
    const float* Wm  = (const float*)d_in[15];
    const float* bm  = (const float*)d_in[16];
    float* out = (float*)d_out;

    static int attr_done = 0;
    if (!attr_done) {
        cudaFuncSetAttribute(scan_kernel, cudaFuncAttributeMaxDynamicSharedMemorySize, SCAN_SMEM);
        attr_done = 1;
    }

    init_kernel<<<512, 256>>>();
    gate_kernel<<<dim3(128, 8), 256>>>(D, Q, PM, W1, b1, W2);
    softmax_kernel<<<64, 256>>>();
    drw_kernel<<<dim3(128, 16), 256>>>(D, Wr, br, Wx, bx);
    scan_kernel<<<NCTA, 256, SCAN_SMEM>>>(Ur, U, bur, bu, out + Bsz * Hsz);
    nextmem_kernel<<<64, 256>>>(PM, Q, Wm, bm, out, out + Bsz * Hsz);
}

// round 14
// speedup vs baseline: 1.5104x; 1.0702x over previous
#include <cuda_runtime.h>
#include <cuda_fp16.h>
#include <math.h>
#include <stdint.h>

#define Bsz 64
#define Ssz 256
#define Hsz 1024
#define BS  16384
#define NCTA 128
#define NISL 64

__device__ __align__(16) float g_Drw[(size_t)BS * 2048];
__device__ __align__(16) float g_Zp[8 * BS];
__device__ __align__(16) float g_G[BS];
__device__ __align__(256) unsigned g_hf[2][2][4][4096];  // [buf][bhalf][chunk][b*128 + swizzled k-word]
__device__ volatile unsigned g_bar_arr2[2 * 32];          // per-island, 128B apart
__device__ volatile unsigned g_bar_gen2[2 * 32];

#define PA 20
#define PB 132
#define SWROW 512

__device__ __forceinline__ unsigned f2tf(float x) {
    unsigned r; asm("cvt.rna.tf32.f32 %0, %1;" : "=r"(r) : "f"(x)); return r;
}
__device__ __forceinline__ void mma8(float* c, const unsigned* a, const unsigned* b) {
    asm volatile("mma.sync.aligned.m16n8k8.row.col.f32.tf32.tf32.f32 "
                 "{%0,%1,%2,%3},{%4,%5,%6,%7},{%8,%9},{%0,%1,%2,%3};"
                 : "+f"(c[0]), "+f"(c[1]), "+f"(c[2]), "+f"(c[3])
                 : "r"(a[0]), "r"(a[1]), "r"(a[2]), "r"(a[3]), "r"(b[0]), "r"(b[1]));
}
__device__ __forceinline__ void mmah(float* c, const unsigned* a, const unsigned* b) {
    asm volatile("mma.sync.aligned.m16n8k16.row.col.f32.f16.f16.f32 "
                 "{%0,%1,%2,%3},{%4,%5,%6,%7},{%8,%9},{%0,%1,%2,%3};"
                 : "+f"(c[0]), "+f"(c[1]), "+f"(c[2]), "+f"(c[3])
                 : "r"(a[0]), "r"(a[1]), "r"(a[2]), "r"(a[3]), "r"(b[0]), "r"(b[1]));
}

__device__ __forceinline__ void tile_mma(const unsigned* sA, const unsigned* sB,
                                         float c[2][8][4], int lane, int wm, int wn) {
    const int q = lane >> 2, la3 = lane & 3;
#pragma unroll
    for (int kk = 0; kk < 16; kk += 8) {
        unsigned a[2][4];
#pragma unroll
        for (int mt = 0; mt < 2; mt++) {
            int r = wm * 32 + mt * 16 + q, cc = kk + la3;
            a[mt][0] = sA[r * PA + cc];     a[mt][1] = sA[(r + 8) * PA + cc];
            a[mt][2] = sA[r * PA + cc + 4]; a[mt][3] = sA[(r + 8) * PA + cc + 4];
        }
        int kx = kk + la3, cb = q * 16 + wn * 8;
        uint4 b0 = *(const uint4*)&sB[kx * PB + cb];
        uint4 b1 = *(const uint4*)&sB[kx * PB + cb + 4];
        uint4 b2 = *(const uint4*)&sB[(kx + 4) * PB + cb];
        uint4 b3 = *(const uint4*)&sB[(kx + 4) * PB + cb + 4];
        unsigned bf[8][2] = {{b0.x,b2.x},{b0.y,b2.y},{b0.z,b2.z},{b0.w,b2.w},
                             {b1.x,b3.x},{b1.y,b3.y},{b1.z,b3.z},{b1.w,b3.w}};
#pragma unroll
        for (int mt = 0; mt < 2; mt++)
#pragma unroll
            for (int nt = 0; nt < 8; nt++) mma8(c[mt][nt], a[mt], bf[nt]);
    }
}

__global__ void init_kernel() {
    int i = blockIdx.x * blockDim.x + threadIdx.x;
    if (i < 64) { g_bar_arr2[i] = 0; g_bar_gen2[i] = 0; }
    if (i < 2 * 2 * 4 * 4096) ((unsigned*)g_hf)[i] = 0u;
}

// ---------------- gate GEMM ----------------
__global__ void __launch_bounds__(256) gate_kernel(
    const float* __restrict__ D, const float* __restrict__ Q, const float* __restrict__ PM,
    const float* __restrict__ W1, const float* __restrict__ b1, const float* __restrict__ W2)
{
    __shared__ __align__(16) unsigned sA[2 * 128 * PA];
    __shared__ __align__(16) unsigned sB[2 * 16 * PB];
    __shared__ float sRed[2][128];
    const int m0 = blockIdx.x * 128, n0 = blockIdx.y * 128;
    const int tid = threadIdx.x, lane = tid & 31, wid = tid >> 5, wm = wid & 3, wn = wid >> 2;
    float c[2][8][4];
#pragma unroll
    for (int i = 0; i < 2; i++)
#pragma unroll
        for (int j = 0; j < 8; j++)
#pragma unroll
            for (int k = 0; k < 4; k++) c[i][j][k] = 0.f;
    const int am = tid >> 1, ak = (tid & 1) * 8, bk = tid >> 4;
    float ra[8], rb[8];
    auto loadAB = [&](int k0) {
        const int qd = k0 >> 10, kk = (k0 & 1023) + ak;
        const int r = m0 + am, b = r >> 8;
        const float4* dp = (const float4*)(D + (size_t)r * Hsz + kk);
        const float4* op = (const float4*)((((qd & 1) == 0) ? Q : PM) + (size_t)b * Hsz + kk);
        float4 d0 = dp[0], d1 = dp[1], o0 = op[0], o1 = op[1];
        if (qd < 2) {
            ra[0] = d0.x * o0.x; ra[1] = d0.y * o0.y; ra[2] = d0.z * o0.z; ra[3] = d0.w * o0.w;
            ra[4] = d1.x * o1.x; ra[5] = d1.y * o1.y; ra[6] = d1.z * o1.z; ra[7] = d1.w * o1.w;
        } else {
            ra[0] = fabsf(d0.x - o0.x); ra[1] = fabsf(d0.y - o0.y); ra[2] = fabsf(d0.z - o0.z); ra[3] = fabsf(d0.w - o0.w);
            ra[4] = fabsf(d1.x - o1.x); ra[5] = fabsf(d1.y - o1.y); ra[6] = fabsf(d1.z - o1.z); ra[7] = fabsf(d1.w - o1.w);
        }
        const float4* wp = (const float4*)(W1 + (size_t)(k0 + bk) * Hsz + n0 + (tid & 15) * 8);
        float4 w0 = wp[0], w1 = wp[1];
        rb[0] = w0.x; rb[1] = w0.y; rb[2] = w0.z; rb[3] = w0.w;
        rb[4] = w1.x; rb[5] = w1.y; rb[6] = w1.z; rb[7] = w1.w;
    };
    auto storeAB = [&](int bsel) {
        unsigned* pA = sA + bsel * 128 * PA;
        unsigned* pB = sB + bsel * 16 * PB;
#pragma unroll
        for (int i = 0; i < 8; i++) pA[am * PA + ak + i] = f2tf(ra[i]);
#pragma unroll
        for (int i = 0; i < 8; i++) pB[bk * PB + i * 16 + (tid & 15)] = f2tf(rb[i]);
    };
    loadAB(0); storeAB(0); __syncthreads();
    int cur = 0;
    for (int k0 = 0; k0 < 4096; k0 += 16) {
        const bool more = (k0 + 16) < 4096;
        if (more) loadAB(k0 + 16);
        tile_mma(sA + cur * 128 * PA, sB + cur * 16 * PB, c, lane, wm, wn);
        if (more) storeAB(cur ^ 1);
        __syncthreads();
        cur ^= 1;
    }
#pragma unroll
    for (int mt = 0; mt < 2; mt++) {
        float s0 = 0.f, s1 = 0.f;
#pragma unroll
        for (int nt = 0; nt < 8; nt++) {
            int nc = n0 + wn * 64 + nt * 8 + (lane & 3) * 2;
            float bb0 = b1[nc], bb1 = b1[nc + 1];
            float w0 = W2[nc], w1 = W2[nc + 1];
            s0 += tanhf(c[mt][nt][0] + bb0) * w0 + tanhf(c[mt][nt][1] + bb1) * w1;
            s1 += tanhf(c[mt][nt][2] + bb0) * w0 + tanhf(c[mt][nt][3] + bb1) * w1;
        }
        s0 += __shfl_xor_sync(0xffffffffu, s0, 1); s0 += __shfl_xor_sync(0xffffffffu, s0, 2);
        s1 += __shfl_xor_sync(0xffffffffu, s1, 1); s1 += __shfl_xor_sync(0xffffffffu, s1, 2);
        if ((lane & 3) == 0) {
            int rl = wm * 32 + mt * 16 + (lane >> 2);
            sRed[wn][rl] = s0; sRed[wn][rl + 8] = s1;
        }
    }
    __syncthreads();
    if (tid < 128) g_Zp[blockIdx.y * BS + m0 + tid] = sRed[0][tid] + sRed[1][tid];
}

__global__ void __launch_bounds__(256) softmax_kernel() {
    __shared__ float red[256];
    const int b = blockIdx.x, s = threadIdx.x;
    float v = 0.f;
#pragma unroll
    for (int p = 0; p < 8; p++) v += g_Zp[p * BS + b * Ssz + s];
    red[s] = v; __syncthreads();
    for (int o = 128; o > 0; o >>= 1) { if (s < o) red[s] = fmaxf(red[s], red[s + o]); __syncthreads(); }
    float mx = red[0]; __syncthreads();
    float e = expf(v - mx);
    red[s] = e; __syncthreads();
    for (int o = 128; o > 0; o >>= 1) { if (s < o) red[s] += red[s + o]; __syncthreads(); }
    g_G[b * Ssz + s] = e / red[0];
}

// ---------------- Dr|Dw ----------------
__global__ void __launch_bounds__(256) drw_kernel(
    const float* __restrict__ D, const float* __restrict__ Wr, const float* __restrict__ br,
    const float* __restrict__ Wx, const float* __restrict__ bx)
{
    __shared__ __align__(16) unsigned sA[2 * 128 * PA];
    __shared__ __align__(16) unsigned sB[2 * 16 * PB];
    const int m0 = blockIdx.x * 128, n0g = blockIdx.y * 128;
    const float* W = (n0g < 1024) ? Wr : Wx;
    const float* bias = (n0g < 1024) ? br : bx;
    const int n0 = n0g & 1023;
    const int tid = threadIdx.x, lane = tid & 31, wid = tid >> 5, wm = wid & 3, wn = wid >> 2;
    float c[2][8][4];
#pragma unroll
    for (int i = 0; i < 2; i++)
#pragma unroll
        for (int j = 0; j < 8; j++)
#pragma unroll
            for (int k = 0; k < 4; k++) c[i][j][k] = 0.f;
    const int am = tid >> 1, ak = (tid & 1) * 8, bk = tid >> 4;
    float ra[8], rb[8];
    auto loadAB = [&](int k0) {
        const float4* dp = (const float4*)(D + (size_t)(m0 + am) * Hsz + k0 + ak);
        float4 d0 = dp[0], d1 = dp[1];
        ra[0] = d0.x; ra[1] = d0.y; ra[2] = d0.z; ra[3] = d0.w;
        ra[4] = d1.x; ra[5] = d1.y; ra[6] = d1.z; ra[7] = d1.w;
        const float4* wp = (const float4*)(W + (size_t)(k0 + bk) * Hsz + n0 + (tid & 15) * 8);
        float4 w0 = wp[0], w1 = wp[1];
        rb[0] = w0.x; rb[1] = w0.y; rb[2] = w0.z; rb[3] = w0.w;
        rb[4] = w1.x; rb[5] = w1.y; rb[6] = w1.z; rb[7] = w1.w;
    };
    auto storeAB = [&](int bsel) {
        unsigned* pA = sA + bsel * 128 * PA;
        unsigned* pB = sB + bsel * 16 * PB;
#pragma unroll
        for (int i = 0; i < 8; i++) pA[am * PA + ak + i] = f2tf(ra[i]);
#pragma unroll
        for (int i = 0; i < 8; i++) pB[bk * PB + i * 16 + (tid & 15)] = f2tf(rb[i]);
    };
    loadAB(0); storeAB(0); __syncthreads();
    int cur = 0;
    for (int k0 = 0; k0 < 1024; k0 += 16) {
        const bool more = (k0 + 16) < 1024;
        if (more) loadAB(k0 + 16);
        tile_mma(sA + cur * 128 * PA, sB + cur * 16 * PB, c, lane, wm, wn);
        if (more) storeAB(cur ^ 1);
        __syncthreads();
        cur ^= 1;
    }
#pragma unroll
    for (int mt = 0; mt < 2; mt++)
#pragma unroll
        for (int nt = 0; nt < 8; nt++) {
            int nl = wn * 64 + nt * 8 + (lane & 3) * 2;
            int r0 = m0 + wm * 32 + mt * 16 + (lane >> 2);
            float bb0 = bias[n0 + nl], bb1 = bias[n0 + nl + 1];
            *(float2*)&g_Drw[(size_t)r0 * 2048 + n0g + nl] = make_float2(c[mt][nt][0] + bb0, c[mt][nt][1] + bb1);
            *(float2*)&g_Drw[(size_t)(r0 + 8) * 2048 + n0g + nl] = make_float2(c[mt][nt][2] + bb0, c[mt][nt][3] + bb1);
        }
}

// ---------------- persistent scan: fp16, batch-split, ring-4, island barriers ----------------
// words: ring 4*4096 | sW 32*512 | sP 32*33 | bias 32 | mbar 8
#define R_RING 0
#define R_SW   16384
#define R_SP   (R_SW + 16384)
#define R_BIAS (R_SP + 32 * 33)
#define R_MB   (R_BIAS + 32)
#define SCAN_WORDS (R_MB + 8)
#define SCAN_SMEM  (SCAN_WORDS * 4 + 1024)

__device__ __forceinline__ void wait_par(unsigned mba, unsigned par) {
    asm volatile("{\n\t.reg .pred P1;\n\tWL_%=:\n\t"
        "mbarrier.try_wait.parity.acquire.cta.shared::cta.b64 P1, [%0], %1, 0x989680;\n\t"
        "@P1 bra.uni WD_%=;\n\tbra.uni WL_%=;\n\tWD_%=:\n\t}"
        :: "r"(mba), "r"(par) : "memory");
}

__device__ __forceinline__ void gbar_isl(int bh) {
    __syncthreads();
    if (threadIdx.x == 0) {
        __threadfence();
        volatile unsigned* arr = &g_bar_arr2[bh * 32];
        volatile unsigned* gen = &g_bar_gen2[bh * 32];
        unsigned g = *gen;
        if (atomicAdd((unsigned*)arr, 1u) == NISL - 1) {
            *arr = 0;
            __threadfence();
            *gen = g + 1;
        } else {
            while (*gen == g) __nanosleep(32);
            __threadfence();
        }
    }
    __syncthreads();
}

__global__ void __launch_bounds__(256, 1) scan_kernel(
    const float* __restrict__ Ur, const float* __restrict__ U,
    const float* __restrict__ bur, const float* __restrict__ bu,
    float* __restrict__ hs)
{
    extern __shared__ __align__(16) unsigned dynraw[];
    unsigned* dyn = (unsigned*)(((uintptr_t)dynraw + 1023) & ~(uintptr_t)1023);
    unsigned* ring = dyn + R_RING;
    unsigned* sW = dyn + R_SW;
    float* sP = (float*)(dyn + R_SP);
    float* sBias = (float*)(dyn + R_BIAS);
    unsigned mb0 = (unsigned)__cvta_generic_to_shared(dyn + R_MB);
    unsigned ring_u32 = (unsigned)__cvta_generic_to_shared(ring);

    const int jc = blockIdx.x & 63;          // column group (16 cols)
    const int bh = blockIdx.x >> 6;          // batch half (independent island)
    const int tid = threadIdx.x, lane = tid & 31, wid = tid >> 5;
    const int wm = wid & 1, wn = wid >> 1, q = lane >> 2, la3 = lane & 3;

    for (int idx = tid; idx < 16 * 1024; idx += 256) {
        int n = idx & 31, k2 = idx >> 5;
        int k = k2 * 2;
        float v0, v1;
        if (n < 16) { v0 = Ur[(size_t)k * Hsz + jc * 16 + n];       v1 = Ur[(size_t)(k + 1) * Hsz + jc * 16 + n]; }
        else        { v0 = U[(size_t)k * Hsz + jc * 16 + (n - 16)]; v1 = U[(size_t)(k + 1) * Hsz + jc * 16 + (n - 16)]; }
        __half2 p = __floats2half2_rn(v0, v1);
        sW[n * SWROW + (k2 ^ ((n & 7) << 2))] = *(unsigned*)&p;
    }
    if (tid < 16)      sBias[tid] = bur[jc * 16 + tid];
    else if (tid < 32) sBias[tid] = bu[jc * 16 + tid - 16];
    if (tid == 0) {
#pragma unroll
        for (int p = 0; p < 4; p++)
            asm volatile("mbarrier.init.shared.b64 [%0], 1;" :: "r"(mb0 + p * 8) : "memory");
        asm volatile("fence.proxy.async.shared::cta;" ::: "memory");
    }
    __syncthreads();

    const int bb = tid >> 3, cp = (tid & 7) * 2;
    const int gb = bh * 32 + bb;
    const int kc_own = jc >> 4;
    const int wword = (jc & 15) * 8 + (tid & 7);
    const int wsw = (bb & 7) << 2;
    const int asw = q << 2;
    float hh[2] = {0.f, 0.f};

    for (int t = 0; t < Ssz; t++) {
        const unsigned* hsrc = (const unsigned*)g_hf[(t & 1) ^ 1][bh];
        if (tid == 0) {
#pragma unroll
            for (int p = 0; p < 4; p++) {
                asm volatile("mbarrier.arrive.expect_tx.shared.b64 _, [%0], 16384;" :: "r"(mb0 + p * 8) : "memory");
                asm volatile("cp.async.bulk.shared::cta.global.mbarrier::complete_tx::bytes [%0], [%1], 16384, [%2];"
                             :: "r"(ring_u32 + p * 16384), "l"(hsrc + p * 4096), "r"(mb0 + p * 8) : "memory");
            }
        }
        const size_t rd = (size_t)gb * Ssz + t;
        float2 dr2 = __ldcg((const float2*)(g_Drw + rd * 2048 + jc * 16 + cp));
        float2 dw2 = __ldcg((const float2*)(g_Drw + rd * 2048 + 1024 + jc * 16 + cp));
        float gt = __ldcg(g_G + rd);

        float acc[4] = {0.f, 0.f, 0.f, 0.f};
#pragma unroll
        for (int cch = 0; cch < 4; cch++) {
            wait_par(mb0 + cch * 8, (unsigned)(t & 1));
            const unsigned* cb = ring + cch * 4096;
            const int rA0 = (wm * 16 + q) * 128, rA1 = rA0 + 8 * 128;
            const int rB = (wn * 8 + q) * SWROW;
#pragma unroll
            for (int ks = 0; ks < 16; ks++) {
                int kw = ks * 8;
                unsigned a[4];
                a[0] = cb[rA0 + ((kw + la3) ^ asw)];
                a[1] = cb[rA1 + ((kw + la3) ^ asw)];
                a[2] = cb[rA0 + ((kw + la3 + 4) ^ asw)];
                a[3] = cb[rA1 + ((kw + la3 + 4) ^ asw)];
                int kp = cch * 128 + kw;
                unsigned bf[2];
                bf[0] = sW[rB + ((kp + la3) ^ asw)];
                bf[1] = sW[rB + ((kp + la3 + 4) ^ asw)];
                mmah(acc, a, bf);
            }
        }
        {
            int r = wm * 16 + q;
            int c0 = wn * 8 + 2 * la3;
            sP[r * 33 + c0] = acc[0]; sP[r * 33 + c0 + 1] = acc[1];
            sP[(r + 8) * 33 + c0] = acc[2]; sP[(r + 8) * 33 + c0 + 1] = acc[3];
        }
        __syncthreads();
        {
            float dr[2] = {dr2.x, dr2.y};
            float dw[2] = {dw2.x, dw2.y};
            float2 ho;
            float* hop = &ho.x;
#pragma unroll
            for (int i = 0; i < 2; i++) {
                int cc = cp + i;
                float r = 1.f / (1.f + expf(-(dr[i] + sP[bb * 33 + cc] + sBias[cc])));
                float ht = tanhf(dw[i] + r * (sP[bb * 33 + 16 + cc] + sBias[16 + cc]));
                hh[i] = gt * ht + (1.f - gt) * hh[i];
                hop[i] = hh[i];
            }
            *(float2*)&hs[rd * Hsz + jc * 16 + cp] = ho;
            __half2 p01 = __floats2half2_rn(hh[0], hh[1]);
            unsigned* dstT = (unsigned*)g_hf[t & 1][bh][kc_own];
            dstT[bb * 128 + (wword ^ wsw)] = *(unsigned*)&p01;
        }
        gbar_isl(bh);
    }
}

// ---------------- next_mem ----------------
__global__ void __launch_bounds__(256) nextmem_kernel(
    const float* __restrict__ PM, const float* __restrict__ Q,
    const float* __restrict__ Wm, const float* __restrict__ bm,
    float* __restrict__ out, const float* __restrict__ hs)
{
    __shared__ float sW6[64 * 16];
    __shared__ float sC[64 * 65];
    const int j = blockIdx.x, tid = threadIdx.x;
    const int n = tid & 15, brow = tid >> 4;
    float acc[4] = {0.f, 0.f, 0.f, 0.f};
    for (int k0 = 0; k0 < 3072; k0 += 64) {
        sW6[tid] = Wm[(size_t)(k0 + (tid >> 4)) * Hsz + j * 16 + (tid & 15)];
        sW6[tid + 256] = Wm[(size_t)(k0 + 16 + (tid >> 4)) * Hsz + j * 16 + (tid & 15)];
        sW6[tid + 512] = Wm[(size_t)(k0 + 32 + (tid >> 4)) * Hsz + j * 16 + (tid & 15)];
        sW6[tid + 768] = Wm[(size_t)(k0 + 48 + (tid >> 4)) * Hsz + j * 16 + (tid & 15)];
#pragma unroll
        for (int it = 0; it < 16; it++) {
            int idx = tid + 256 * it;
            int b = idx >> 6, kk = idx & 63, k = k0 + kk;
            float v = (k < 1024) ? PM[b * Hsz + k]
                    : (k < 2048) ? hs[((size_t)b * Ssz + 255) * Hsz + k - 1024]
                                 : Q[b * Hsz + k - 2048];
            sC[b * 65 + kk] = v;
        }
        __syncthreads();
#pragma unroll 8
        for (int kk = 0; kk < 64; kk++) {
            float w = sW6[kk * 16 + n];
            acc[0] += sC[brow * 65 + kk] * w;
            acc[1] += sC[(brow + 16) * 65 + kk] * w;
            acc[2] += sC[(brow + 32) * 65 + kk] * w;
            acc[3] += sC[(brow + 48) * 65 + kk] * w;
        }
        __syncthreads();
    }
    float bb = bm[j * 16 + n];
    out[(size_t)brow * Hsz + j * 16 + n]        = fmaxf(acc[0] + bb, 0.f);
    out[(size_t)(brow + 16) * Hsz + j * 16 + n] = fmaxf(acc[1] + bb, 0.f);
    out[(size_t)(brow + 32) * Hsz + j * 16 + n] = fmaxf(acc[2] + bb, 0.f);
    out[(size_t)(brow + 48) * Hsz + j * 16 + n] = fmaxf(acc[3] + bb, 0.f);
}

extern "C" void kernel_launch(void* const* d_in, const int* in_sizes, int n_in,
                              void* d_out, int out_size) {
    const float* D   = (const float*)d_in[0];
    const float* Q   = (const float*)d_in[1];
    const float* PM  = (const float*)d_in[2];
    const float* Wr  = (const float*)d_in[3];
    const float* br  = (const float*)d_in[4];
    const float* Ur  = (const float*)d_in[5];
    const float* bur = (const float*)d_in[6];
    const float* Wx  = (const float*)d_in[7];
    const float* bx  = (const float*)d_in[8];
    const float* U   = (const float*)d_in[9];
    const float* bu  = (const float*)d_in[10];
    const float* W1  = (const float*)d_in[11];
    const float* b1  = (const float*)d_in[12];
    const float* W2  = (const float*)d_in[13];
    const float* Wm  = (const float*)d_in[15];
    const float* bm  = (const float*)d_in[16];
    float* out = (float*)d_out;

    static int attr_done = 0;
    if (!attr_done) {
        cudaFuncSetAttribute(scan_kernel, cudaFuncAttributeMaxDynamicSharedMemorySize, SCAN_SMEM);
        attr_done = 1;
    }

    init_kernel<<<512, 256>>>();
    gate_kernel<<<dim3(128, 8), 256>>>(D, Q, PM, W1, b1, W2);
    softmax_kernel<<<64, 256>>>();
    drw_kernel<<<dim3(128, 16), 256>>>(D, Wr, br, Wx, bx);
    scan_kernel<<<NCTA, 256, SCAN_SMEM>>>(Ur, U, bur, bu, out + Bsz * Hsz);
    nextmem_kernel<<<64, 256>>>(PM, Q, Wm, bm, out, out + Bsz * Hsz);
}

// round 15
// speedup vs baseline: 1.7622x; 1.1666x over previous
#include <cuda_runtime.h>
#include <cuda_fp16.h>
#include <math.h>
#include <stdint.h>

#define Bsz 64
#define Ssz 256
#define Hsz 1024
#define BS  16384
#define NCTA 128
#define NISL 64

__device__ __align__(16) float g_Drw[(size_t)BS * 2048];
__device__ __align__(16) float g_Zp[8 * BS];
__device__ __align__(16) float g_G[BS];
__device__ __align__(256) unsigned g_hf[2][2][4][4096];
__device__ volatile unsigned g_bar_arr2[2 * 32];
__device__ volatile unsigned g_bar_gen2[2 * 32];

#define PA2 12
#define PB 132
#define SWROW 512

__device__ __forceinline__ void mmah(float* c, const unsigned* a, const unsigned* b) {
    asm volatile("mma.sync.aligned.m16n8k16.row.col.f32.f16.f16.f32 "
                 "{%0,%1,%2,%3},{%4,%5,%6,%7},{%8,%9},{%0,%1,%2,%3};"
                 : "+f"(c[0]), "+f"(c[1]), "+f"(c[2]), "+f"(c[3])
                 : "r"(a[0]), "r"(a[1]), "r"(a[2]), "r"(a[3]), "r"(b[0]), "r"(b[1]));
}
__device__ __forceinline__ unsigned h2u(float x, float y) {
    __half2 p = __floats2half2_rn(x, y);
    return *(unsigned*)&p;
}

// CTA 128x128 fp16 tile over one k16 slab. sA[m][kpair] pitch PA2; sB[kpair][(n&7)*16+(n>>3)]
__device__ __forceinline__ void tile_mma_h(const unsigned* sA, const unsigned* sB,
                                           float c[2][8][4], int lane, int wm, int wn) {
    const int q = lane >> 2, la3 = lane & 3;
    unsigned a[2][4];
#pragma unroll
    for (int mt = 0; mt < 2; mt++) {
        int r = wm * 32 + mt * 16 + q;
        a[mt][0] = sA[r * PA2 + la3];       a[mt][1] = sA[(r + 8) * PA2 + la3];
        a[mt][2] = sA[r * PA2 + la3 + 4];   a[mt][3] = sA[(r + 8) * PA2 + la3 + 4];
    }
    const int cb = q * 16 + wn * 8;
    uint4 b0 = *(const uint4*)&sB[la3 * PB + cb];
    uint4 b1 = *(const uint4*)&sB[la3 * PB + cb + 4];
    uint4 b2 = *(const uint4*)&sB[(la3 + 4) * PB + cb];
    uint4 b3 = *(const uint4*)&sB[(la3 + 4) * PB + cb + 4];
    unsigned bf[8][2] = {{b0.x,b2.x},{b0.y,b2.y},{b0.z,b2.z},{b0.w,b2.w},
                         {b1.x,b3.x},{b1.y,b3.y},{b1.z,b3.z},{b1.w,b3.w}};
#pragma unroll
    for (int mt = 0; mt < 2; mt++)
#pragma unroll
        for (int nt = 0; nt < 8; nt++) mmah(c[mt][nt], a[mt], bf[nt]);
}

__global__ void init_kernel() {
    int i = blockIdx.x * blockDim.x + threadIdx.x;
    if (i < 64) { g_bar_arr2[i] = 0; g_bar_gen2[i] = 0; }
    if (i < 2 * 2 * 4 * 4096) ((unsigned*)g_hf)[i] = 0u;
}

// ---------------- gate GEMM (fp16) ----------------
__global__ void __launch_bounds__(256) gate_kernel(
    const float* __restrict__ D, const float* __restrict__ Q, const float* __restrict__ PM,
    const float* __restrict__ W1, const float* __restrict__ b1, const float* __restrict__ W2)
{
    __shared__ __align__(16) unsigned sA[2 * 128 * PA2];
    __shared__ __align__(16) unsigned sB[2 * 8 * PB];
    __shared__ float sRed[2][128];
    const int m0 = blockIdx.x * 128, n0 = blockIdx.y * 128;
    const int tid = threadIdx.x, lane = tid & 31, wid = tid >> 5, wm = wid & 3, wn = wid >> 2;
    float c[2][8][4];
#pragma unroll
    for (int i = 0; i < 2; i++)
#pragma unroll
        for (int j = 0; j < 8; j++)
#pragma unroll
            for (int k = 0; k < 4; k++) c[i][j][k] = 0.f;
    const int am = tid >> 1, ak = (tid & 1) * 8, ak2 = (tid & 1) * 4;
    const int kp = tid >> 5, nb = (tid & 31) * 4;
    float ra[8]; float rb0[4], rb1[4];
    auto loadAB = [&](int k0) {
        const int qd = k0 >> 10, kk = (k0 & 1023) + ak;
        const int r = m0 + am, b = r >> 8;
        const float4* dp = (const float4*)(D + (size_t)r * Hsz + kk);
        const float4* op = (const float4*)((((qd & 1) == 0) ? Q : PM) + (size_t)b * Hsz + kk);
        float4 d0 = dp[0], d1 = dp[1], o0 = op[0], o1 = op[1];
        if (qd < 2) {
            ra[0] = d0.x * o0.x; ra[1] = d0.y * o0.y; ra[2] = d0.z * o0.z; ra[3] = d0.w * o0.w;
            ra[4] = d1.x * o1.x; ra[5] = d1.y * o1.y; ra[6] = d1.z * o1.z; ra[7] = d1.w * o1.w;
        } else {
            ra[0] = fabsf(d0.x - o0.x); ra[1] = fabsf(d0.y - o0.y); ra[2] = fabsf(d0.z - o0.z); ra[3] = fabsf(d0.w - o0.w);
            ra[4] = fabsf(d1.x - o1.x); ra[5] = fabsf(d1.y - o1.y); ra[6] = fabsf(d1.z - o1.z); ra[7] = fabsf(d1.w - o1.w);
        }
        float4 w0 = *(const float4*)(W1 + (size_t)(k0 + 2 * kp) * Hsz + n0 + nb);
        float4 w1 = *(const float4*)(W1 + (size_t)(k0 + 2 * kp + 1) * Hsz + n0 + nb);
        rb0[0] = w0.x; rb0[1] = w0.y; rb0[2] = w0.z; rb0[3] = w0.w;
        rb1[0] = w1.x; rb1[1] = w1.y; rb1[2] = w1.z; rb1[3] = w1.w;
    };
    auto storeAB = [&](int bsel) {
        unsigned* pA = sA + bsel * 128 * PA2;
        unsigned* pB = sB + bsel * 8 * PB;
#pragma unroll
        for (int i = 0; i < 4; i++) pA[am * PA2 + ak2 + i] = h2u(ra[2 * i], ra[2 * i + 1]);
#pragma unroll
        for (int i = 0; i < 4; i++) {
            int n = nb + i;
            pB[kp * PB + (n & 7) * 16 + (n >> 3)] = h2u(rb0[i], rb1[i]);
        }
    };
    loadAB(0); storeAB(0); __syncthreads();
    int cur = 0;
    for (int k0 = 0; k0 < 4096; k0 += 16) {
        const bool more = (k0 + 16) < 4096;
        if (more) loadAB(k0 + 16);
        tile_mma_h(sA + cur * 128 * PA2, sB + cur * 8 * PB, c, lane, wm, wn);
        if (more) storeAB(cur ^ 1);
        __syncthreads();
        cur ^= 1;
    }
#pragma unroll
    for (int mt = 0; mt < 2; mt++) {
        float s0 = 0.f, s1 = 0.f;
#pragma unroll
        for (int nt = 0; nt < 8; nt++) {
            int nc = n0 + wn * 64 + nt * 8 + (lane & 3) * 2;
            float bb0 = b1[nc], bb1 = b1[nc + 1];
            float w0 = W2[nc], w1 = W2[nc + 1];
            s0 += tanhf(c[mt][nt][0] + bb0) * w0 + tanhf(c[mt][nt][1] + bb1) * w1;
            s1 += tanhf(c[mt][nt][2] + bb0) * w0 + tanhf(c[mt][nt][3] + bb1) * w1;
        }
        s0 += __shfl_xor_sync(0xffffffffu, s0, 1); s0 += __shfl_xor_sync(0xffffffffu, s0, 2);
        s1 += __shfl_xor_sync(0xffffffffu, s1, 1); s1 += __shfl_xor_sync(0xffffffffu, s1, 2);
        if ((lane & 3) == 0) {
            int rl = wm * 32 + mt * 16 + (lane >> 2);
            sRed[wn][rl] = s0; sRed[wn][rl + 8] = s1;
        }
    }
    __syncthreads();
    if (tid < 128) g_Zp[blockIdx.y * BS + m0 + tid] = sRed[0][tid] + sRed[1][tid];
}

__global__ void __launch_bounds__(256) softmax_kernel() {
    __shared__ float red[256];
    const int b = blockIdx.x, s = threadIdx.x;
    float v = 0.f;
#pragma unroll
    for (int p = 0; p < 8; p++) v += g_Zp[p * BS + b * Ssz + s];
    red[s] = v; __syncthreads();
    for (int o = 128; o > 0; o >>= 1) { if (s < o) red[s] = fmaxf(red[s], red[s + o]); __syncthreads(); }
    float mx = red[0]; __syncthreads();
    float e = expf(v - mx);
    red[s] = e; __syncthreads();
    for (int o = 128; o > 0; o >>= 1) { if (s < o) red[s] += red[s + o]; __syncthreads(); }
    g_G[b * Ssz + s] = e / red[0];
}

// ---------------- Dr|Dw (fp16) ----------------
__global__ void __launch_bounds__(256) drw_kernel(
    const float* __restrict__ D, const float* __restrict__ Wr, const float* __restrict__ br,
    const float* __restrict__ Wx, const float* __restrict__ bx)
{
    __shared__ __align__(16) unsigned sA[2 * 128 * PA2];
    __shared__ __align__(16) unsigned sB[2 * 8 * PB];
    const int m0 = blockIdx.x * 128, n0g = blockIdx.y * 128;
    const float* W = (n0g < 1024) ? Wr : Wx;
    const float* bias = (n0g < 1024) ? br : bx;
    const int n0 = n0g & 1023;
    const int tid = threadIdx.x, lane = tid & 31, wid = tid >> 5, wm = wid & 3, wn = wid >> 2;
    float c[2][8][4];
#pragma unroll
    for (int i = 0; i < 2; i++)
#pragma unroll
        for (int j = 0; j < 8; j++)
#pragma unroll
            for (int k = 0; k < 4; k++) c[i][j][k] = 0.f;
    const int am = tid >> 1, ak = (tid & 1) * 8, ak2 = (tid & 1) * 4;
    const int kp = tid >> 5, nb = (tid & 31) * 4;
    float ra[8]; float rb0[4], rb1[4];
    auto loadAB = [&](int k0) {
        const float4* dp = (const float4*)(D + (size_t)(m0 + am) * Hsz + k0 + ak);
        float4 d0 = dp[0], d1 = dp[1];
        ra[0] = d0.x; ra[1] = d0.y; ra[2] = d0.z; ra[3] = d0.w;
        ra[4] = d1.x; ra[5] = d1.y; ra[6] = d1.z; ra[7] = d1.w;
        float4 w0 = *(const float4*)(W + (size_t)(k0 + 2 * kp) * Hsz + n0 + nb);
        float4 w1 = *(const float4*)(W + (size_t)(k0 + 2 * kp + 1) * Hsz + n0 + nb);
        rb0[0] = w0.x; rb0[1] = w0.y; rb0[2] = w0.z; rb0[3] = w0.w;
        rb1[0] = w1.x; rb1[1] = w1.y; rb1[2] = w1.z; rb1[3] = w1.w;
    };
    auto storeAB = [&](int bsel) {
        unsigned* pA = sA + bsel * 128 * PA2;
        unsigned* pB = sB + bsel * 8 * PB;
#pragma unroll
        for (int i = 0; i < 4; i++) pA[am * PA2 + ak2 + i] = h2u(ra[2 * i], ra[2 * i + 1]);
#pragma unroll
        for (int i = 0; i < 4; i++) {
            int n = nb + i;
            pB[kp * PB + (n & 7) * 16 + (n >> 3)] = h2u(rb0[i], rb1[i]);
        }
    };
    loadAB(0); storeAB(0); __syncthreads();
    int cur = 0;
    for (int k0 = 0; k0 < 1024; k0 += 16) {
        const bool more = (k0 + 16) < 1024;
        if (more) loadAB(k0 + 16);
        tile_mma_h(sA + cur * 128 * PA2, sB + cur * 8 * PB, c, lane, wm, wn);
        if (more) storeAB(cur ^ 1);
        __syncthreads();
        cur ^= 1;
    }
#pragma unroll
    for (int mt = 0; mt < 2; mt++)
#pragma unroll
        for (int nt = 0; nt < 8; nt++) {
            int nl = wn * 64 + nt * 8 + (lane & 3) * 2;
            int r0 = m0 + wm * 32 + mt * 16 + (lane >> 2);
            float bb0 = bias[n0 + nl], bb1 = bias[n0 + nl + 1];
            *(float2*)&g_Drw[(size_t)r0 * 2048 + n0g + nl] = make_float2(c[mt][nt][0] + bb0, c[mt][nt][1] + bb1);
            *(float2*)&g_Drw[(size_t)(r0 + 8) * 2048 + n0g + nl] = make_float2(c[mt][nt][2] + bb0, c[mt][nt][3] + bb1);
        }
}

// ---------------- persistent scan (R14-verified) ----------------
#define R_RING 0
#define R_SW   16384
#define R_SP   (R_SW + 16384)
#define R_BIAS (R_SP + 32 * 33)
#define R_MB   (R_BIAS + 32)
#define SCAN_WORDS (R_MB + 8)
#define SCAN_SMEM  (SCAN_WORDS * 4 + 1024)

__device__ __forceinline__ void wait_par(unsigned mba, unsigned par) {
    asm volatile("{\n\t.reg .pred P1;\n\tWL_%=:\n\t"
        "mbarrier.try_wait.parity.acquire.cta.shared::cta.b64 P1, [%0], %1, 0x989680;\n\t"
        "@P1 bra.uni WD_%=;\n\tbra.uni WL_%=;\n\tWD_%=:\n\t}"
        :: "r"(mba), "r"(par) : "memory");
}

__device__ __forceinline__ void gbar_isl(int bh) {
    __syncthreads();
    if (threadIdx.x == 0) {
        __threadfence();
        volatile unsigned* arr = &g_bar_arr2[bh * 32];
        volatile unsigned* gen = &g_bar_gen2[bh * 32];
        unsigned g = *gen;
        if (atomicAdd((unsigned*)arr, 1u) == NISL - 1) {
            *arr = 0;
            __threadfence();
            *gen = g + 1;
        } else {
            while (*gen == g) __nanosleep(32);
            __threadfence();
        }
    }
    __syncthreads();
}

__global__ void __launch_bounds__(256, 1) scan_kernel(
    const float* __restrict__ Ur, const float* __restrict__ U,
    const float* __restrict__ bur, const float* __restrict__ bu,
    float* __restrict__ hs)
{
    extern __shared__ __align__(16) unsigned dynraw[];
    unsigned* dyn = (unsigned*)(((uintptr_t)dynraw + 1023) & ~(uintptr_t)1023);
    unsigned* ring = dyn + R_RING;
    unsigned* sW = dyn + R_SW;
    float* sP = (float*)(dyn + R_SP);
    float* sBias = (float*)(dyn + R_BIAS);
    unsigned mb0 = (unsigned)__cvta_generic_to_shared(dyn + R_MB);
    unsigned ring_u32 = (unsigned)__cvta_generic_to_shared(ring);

    const int jc = blockIdx.x & 63;
    const int bh = blockIdx.x >> 6;
    const int tid = threadIdx.x, lane = tid & 31, wid = tid >> 5;
    const int wm = wid & 1, wn = wid >> 1, q = lane >> 2, la3 = lane & 3;

    for (int idx = tid; idx < 16 * 1024; idx += 256) {
        int n = idx & 31, k2 = idx >> 5;
        int k = k2 * 2;
        float v0, v1;
        if (n < 16) { v0 = Ur[(size_t)k * Hsz + jc * 16 + n];       v1 = Ur[(size_t)(k + 1) * Hsz + jc * 16 + n]; }
        else        { v0 = U[(size_t)k * Hsz + jc * 16 + (n - 16)]; v1 = U[(size_t)(k + 1) * Hsz + jc * 16 + (n - 16)]; }
        sW[n * SWROW + (k2 ^ ((n & 7) << 2))] = h2u(v0, v1);
    }
    if (tid < 16)      sBias[tid] = bur[jc * 16 + tid];
    else if (tid < 32) sBias[tid] = bu[jc * 16 + tid - 16];
    if (tid == 0) {
#pragma unroll
        for (int p = 0; p < 4; p++)
            asm volatile("mbarrier.init.shared.b64 [%0], 1;" :: "r"(mb0 + p * 8) : "memory");
        asm volatile("fence.proxy.async.shared::cta;" ::: "memory");
    }
    __syncthreads();

    const int bb = tid >> 3, cp = (tid & 7) * 2;
    const int gb = bh * 32 + bb;
    const int kc_own = jc >> 4;
    const int wword = (jc & 15) * 8 + (tid & 7);
    const int wsw = (bb & 7) << 2;
    const int asw = q << 2;
    float hh[2] = {0.f, 0.f};

    for (int t = 0; t < Ssz; t++) {
        const unsigned* hsrc = (const unsigned*)g_hf[(t & 1) ^ 1][bh];
        if (tid == 0) {
#pragma unroll
            for (int p = 0; p < 4; p++) {
                asm volatile("mbarrier.arrive.expect_tx.shared.b64 _, [%0], 16384;" :: "r"(mb0 + p * 8) : "memory");
                asm volatile("cp.async.bulk.shared::cta.global.mbarrier::complete_tx::bytes [%0], [%1], 16384, [%2];"
                             :: "r"(ring_u32 + p * 16384), "l"(hsrc + p * 4096), "r"(mb0 + p * 8) : "memory");
            }
        }
        const size_t rd = (size_t)gb * Ssz + t;
        float2 dr2 = __ldcg((const float2*)(g_Drw + rd * 2048 + jc * 16 + cp));
        float2 dw2 = __ldcg((const float2*)(g_Drw + rd * 2048 + 1024 + jc * 16 + cp));
        float gt = __ldcg(g_G + rd);

        float acc[4] = {0.f, 0.f, 0.f, 0.f};
#pragma unroll
        for (int cch = 0; cch < 4; cch++) {
            wait_par(mb0 + cch * 8, (unsigned)(t & 1));
            const unsigned* cb = ring + cch * 4096;
            const int rA0 = (wm * 16 + q) * 128, rA1 = rA0 + 8 * 128;
            const int rB = (wn * 8 + q) * SWROW;
#pragma unroll
            for (int ks = 0; ks < 16; ks++) {
                int kw = ks * 8;
                unsigned a[4];
                a[0] = cb[rA0 + ((kw + la3) ^ asw)];
                a[1] = cb[rA1 + ((kw + la3) ^ asw)];
                a[2] = cb[rA0 + ((kw + la3 + 4) ^ asw)];
                a[3] = cb[rA1 + ((kw + la3 + 4) ^ asw)];
                int kpp = cch * 128 + kw;
                unsigned bf[2];
                bf[0] = sW[rB + ((kpp + la3) ^ asw)];
                bf[1] = sW[rB + ((kpp + la3 + 4) ^ asw)];
                mmah(acc, a, bf);
            }
        }
        {
            int r = wm * 16 + q;
            int c0 = wn * 8 + 2 * la3;
            sP[r * 33 + c0] = acc[0]; sP[r * 33 + c0 + 1] = acc[1];
            sP[(r + 8) * 33 + c0] = acc[2]; sP[(r + 8) * 33 + c0 + 1] = acc[3];
        }
        __syncthreads();
        {
            float dr[2] = {dr2.x, dr2.y};
            float dw[2] = {dw2.x, dw2.y};
            float2 ho;
            float* hop = &ho.x;
#pragma unroll
            for (int i = 0; i < 2; i++) {
                int cc = cp + i;
                float r = 1.f / (1.f + expf(-(dr[i] + sP[bb * 33 + cc] + sBias[cc])));
                float ht = tanhf(dw[i] + r * (sP[bb * 33 + 16 + cc] + sBias[16 + cc]));
                hh[i] = gt * ht + (1.f - gt) * hh[i];
                hop[i] = hh[i];
            }
            *(float2*)&hs[rd * Hsz + jc * 16 + cp] = ho;
            unsigned* dstT = (unsigned*)g_hf[t & 1][bh][kc_own];
            dstT[bb * 128 + (wword ^ wsw)] = h2u(hh[0], hh[1]);
        }
        gbar_isl(bh);
    }
}

// ---------------- next_mem ----------------
__global__ void __launch_bounds__(256) nextmem_kernel(
    const float* __restrict__ PM, const float* __restrict__ Q,
    const float* __restrict__ Wm, const float* __restrict__ bm,
    float* __restrict__ out, const float* __restrict__ hs)
{
    __shared__ float sW6[64 * 16];
    __shared__ float sC[64 * 65];
    const int j = blockIdx.x, tid = threadIdx.x;
    const int n = tid & 15, brow = tid >> 4;
    float acc[4] = {0.f, 0.f, 0.f, 0.f};
    for (int k0 = 0; k0 < 3072; k0 += 64) {
        sW6[tid] = Wm[(size_t)(k0 + (tid >> 4)) * Hsz + j * 16 + (tid & 15)];
        sW6[tid + 256] = Wm[(size_t)(k0 + 16 + (tid >> 4)) * Hsz + j * 16 + (tid & 15)];
        sW6[tid + 512] = Wm[(size_t)(k0 + 32 + (tid >> 4)) * Hsz + j * 16 + (tid & 15)];
        sW6[tid + 768] = Wm[(size_t)(k0 + 48 + (tid >> 4)) * Hsz + j * 16 + (tid & 15)];
#pragma unroll
        for (int it = 0; it < 16; it++) {
            int idx = tid + 256 * it;
            int b = idx >> 6, kk = idx & 63, k = k0 + kk;
            float v = (k < 1024) ? PM[b * Hsz + k]
                    : (k < 2048) ? hs[((size_t)b * Ssz + 255) * Hsz + k - 1024]
                                 : Q[b * Hsz + k - 2048];
            sC[b * 65 + kk] = v;
        }
        __syncthreads();
#pragma unroll 8
        for (int kk = 0; kk < 64; kk++) {
            float w = sW6[kk * 16 + n];
            acc[0] += sC[brow * 65 + kk] * w;
            acc[1] += sC[(brow + 16) * 65 + kk] * w;
            acc[2] += sC[(brow + 32) * 65 + kk] * w;
            acc[3] += sC[(brow + 48) * 65 + kk] * w;
        }
        __syncthreads();
    }
    float bb = bm[j * 16 + n];
    out[(size_t)brow * Hsz + j * 16 + n]        = fmaxf(acc[0] + bb, 0.f);
    out[(size_t)(brow + 16) * Hsz + j * 16 + n] = fmaxf(acc[1] + bb, 0.f);
    out[(size_t)(brow + 32) * Hsz + j * 16 + n] = fmaxf(acc[2] + bb, 0.f);
    out[(size_t)(brow + 48) * Hsz + j * 16 + n] = fmaxf(acc[3] + bb, 0.f);
}

extern "C" void kernel_launch(void* const* d_in, const int* in_sizes, int n_in,
                              void* d_out, int out_size) {
    const float* D   = (const float*)d_in[0];
    const float* Q   = (const float*)d_in[1];
    const float* PM  = (const float*)d_in[2];
    const float* Wr  = (const float*)d_in[3];
    const float* br  = (const float*)d_in[4];
    const float* Ur  = (const float*)d_in[5];
    const float* bur = (const float*)d_in[6];
    const float* Wx  = (const float*)d_in[7];
    const float* bx  = (const float*)d_in[8];
    const float* U   = (const float*)d_in[9];
    const float* bu  = (const float*)d_in[10];
    const float* W1  = (const float*)d_in[11];
    const float* b1  = (const float*)d_in[12];
    const float* W2  = (const float*)d_in[13];
    const float* Wm  = (const float*)d_in[15];
    const float* bm  = (const float*)d_in[16];
    float* out = (float*)d_out;

    static int attr_done = 0;
    if (!attr_done) {
        cudaFuncSetAttribute(scan_kernel, cudaFuncAttributeMaxDynamicSharedMemorySize, SCAN_SMEM);
        attr_done = 1;
    }

    init_kernel<<<512, 256>>>();
    gate_kernel<<<dim3(128, 8), 256>>>(D, Q, PM, W1, b1, W2);
    softmax_kernel<<<64, 256>>>();
    drw_kernel<<<dim3(128, 16), 256>>>(D, Wr, br, Wx, bx);
    scan_kernel<<<NCTA, 256, SCAN_SMEM>>>(Ur, U, bur, bu, out + Bsz * Hsz);
    nextmem_kernel<<<64, 256>>>(PM, Q, Wm, bm, out, out + Bsz * Hsz);
}

// round 16
// speedup vs baseline: 1.8288x; 1.0378x over previous
#include <cuda_runtime.h>
#include <cuda_fp16.h>
#include <math.h>
#include <stdint.h>

#define Bsz 64
#define Ssz 256
#define Hsz 1024
#define BS  16384
#define NCTA 128
#define NISL 64

__device__ __align__(16) float g_Drw[(size_t)BS * 2048];
__device__ __align__(16) float g_Zp[8 * BS];
__device__ __align__(16) float g_G[BS];
__device__ __align__(256) unsigned g_hf[2][2][4][4096];
__device__ volatile unsigned g_grp[2][8][32];
__device__ volatile unsigned g_root[2][32];
__device__ volatile unsigned g_gen[2][32];

#define PA2 12
#define PB 132
#define SWROW 512

__device__ __forceinline__ void mmah(float* c, const unsigned* a, const unsigned* b) {
    asm volatile("mma.sync.aligned.m16n8k16.row.col.f32.f16.f16.f32 "
                 "{%0,%1,%2,%3},{%4,%5,%6,%7},{%8,%9},{%0,%1,%2,%3};"
                 : "+f"(c[0]), "+f"(c[1]), "+f"(c[2]), "+f"(c[3])
                 : "r"(a[0]), "r"(a[1]), "r"(a[2]), "r"(a[3]), "r"(b[0]), "r"(b[1]));
}
__device__ __forceinline__ unsigned h2u(float x, float y) {
    __half2 p = __floats2half2_rn(x, y);
    return *(unsigned*)&p;
}
__device__ __forceinline__ void ldsm4(unsigned r[4], const void* p) {
    unsigned a = (unsigned)__cvta_generic_to_shared(p);
    asm volatile("ldmatrix.sync.aligned.m8n8.x4.shared.b16 {%0,%1,%2,%3}, [%4];"
                 : "=r"(r[0]), "=r"(r[1]), "=r"(r[2]), "=r"(r[3]) : "r"(a));
}
__device__ __forceinline__ void ldsm2(unsigned r[2], const void* p) {
    unsigned a = (unsigned)__cvta_generic_to_shared(p);
    asm volatile("ldmatrix.sync.aligned.m8n8.x2.shared.b16 {%0,%1}, [%2];"
                 : "=r"(r[0]), "=r"(r[1]) : "r"(a));
}

// CTA 128x128 fp16 tile; A via ldmatrix.x4, B via LDS.128 n-interleave
__device__ __forceinline__ void tile_mma_h(const unsigned* sA, const unsigned* sB,
                                           float c[2][8][4], int lane, int wm, int wn) {
    const int q = lane >> 2, la3 = lane & 3;
    unsigned a[2][4];
#pragma unroll
    for (int mt = 0; mt < 2; mt++)
        ldsm4(a[mt], sA + (wm * 32 + mt * 16 + (lane & 15)) * PA2 + (lane >> 4) * 4);
    const int cb = q * 16 + wn * 8;
    uint4 b0 = *(const uint4*)&sB[la3 * PB + cb];
    uint4 b1 = *(const uint4*)&sB[la3 * PB + cb + 4];
    uint4 b2 = *(const uint4*)&sB[(la3 + 4) * PB + cb];
    uint4 b3 = *(const uint4*)&sB[(la3 + 4) * PB + cb + 4];
    unsigned bf[8][2] = {{b0.x,b2.x},{b0.y,b2.y},{b0.z,b2.z},{b0.w,b2.w},
                         {b1.x,b3.x},{b1.y,b3.y},{b1.z,b3.z},{b1.w,b3.w}};
#pragma unroll
    for (int mt = 0; mt < 2; mt++)
#pragma unroll
        for (int nt = 0; nt < 8; nt++) mmah(c[mt][nt], a[mt], bf[nt]);
}

__global__ void init_kernel() {
    int i = blockIdx.x * blockDim.x + threadIdx.x;
    if (i < 2 * 8 * 32) ((volatile unsigned*)g_grp)[i] = 0;
    if (i < 2 * 32) { ((volatile unsigned*)g_root)[i] = 0; ((volatile unsigned*)g_gen)[i] = 0; }
    if (i < 2 * 2 * 4 * 4096) ((unsigned*)g_hf)[i] = 0u;
}

// ---------------- gate GEMM (fp16) ----------------
__global__ void __launch_bounds__(256) gate_kernel(
    const float* __restrict__ D, const float* __restrict__ Q, const float* __restrict__ PM,
    const float* __restrict__ W1, const float* __restrict__ b1, const float* __restrict__ W2)
{
    __shared__ __align__(16) unsigned sA[2 * 128 * PA2];
    __shared__ __align__(16) unsigned sB[2 * 8 * PB];
    __shared__ float sRed[2][128];
    const int m0 = blockIdx.x * 128, n0 = blockIdx.y * 128;
    const int tid = threadIdx.x, lane = tid & 31, wid = tid >> 5, wm = wid & 3, wn = wid >> 2;
    float c[2][8][4];
#pragma unroll
    for (int i = 0; i < 2; i++)
#pragma unroll
        for (int j = 0; j < 8; j++)
#pragma unroll
            for (int k = 0; k < 4; k++) c[i][j][k] = 0.f;
    const int am = tid >> 1, ak = (tid & 1) * 8, ak2 = (tid & 1) * 4;
    const int kp = tid >> 5, nb = (tid & 31) * 4;
    float ra[8]; float rb0[4], rb1[4];
    auto loadAB = [&](int k0) {
        const int qd = k0 >> 10, kk = (k0 & 1023) + ak;
        const int r = m0 + am, b = r >> 8;
        const float4* dp = (const float4*)(D + (size_t)r * Hsz + kk);
        const float4* op = (const float4*)((((qd & 1) == 0) ? Q : PM) + (size_t)b * Hsz + kk);
        float4 d0 = dp[0], d1 = dp[1], o0 = op[0], o1 = op[1];
        if (qd < 2) {
            ra[0] = d0.x * o0.x; ra[1] = d0.y * o0.y; ra[2] = d0.z * o0.z; ra[3] = d0.w * o0.w;
            ra[4] = d1.x * o1.x; ra[5] = d1.y * o1.y; ra[6] = d1.z * o1.z; ra[7] = d1.w * o1.w;
        } else {
            ra[0] = fabsf(d0.x - o0.x); ra[1] = fabsf(d0.y - o0.y); ra[2] = fabsf(d0.z - o0.z); ra[3] = fabsf(d0.w - o0.w);
            ra[4] = fabsf(d1.x - o1.x); ra[5] = fabsf(d1.y - o1.y); ra[6] = fabsf(d1.z - o1.z); ra[7] = fabsf(d1.w - o1.w);
        }
        float4 w0 = *(const float4*)(W1 + (size_t)(k0 + 2 * kp) * Hsz + n0 + nb);
        float4 w1 = *(const float4*)(W1 + (size_t)(k0 + 2 * kp + 1) * Hsz + n0 + nb);
        rb0[0] = w0.x; rb0[1] = w0.y; rb0[2] = w0.z; rb0[3] = w0.w;
        rb1[0] = w1.x; rb1[1] = w1.y; rb1[2] = w1.z; rb1[3] = w1.w;
    };
    auto storeAB = [&](int bsel) {
        unsigned* pA = sA + bsel * 128 * PA2;
        unsigned* pB = sB + bsel * 8 * PB;
#pragma unroll
        for (int i = 0; i < 4; i++) pA[am * PA2 + ak2 + i] = h2u(ra[2 * i], ra[2 * i + 1]);
#pragma unroll
        for (int i = 0; i < 4; i++) {
            int n = nb + i;
            pB[kp * PB + (n & 7) * 16 + (n >> 3)] = h2u(rb0[i], rb1[i]);
        }
    };
    loadAB(0); storeAB(0); __syncthreads();
    int cur = 0;
    for (int k0 = 0; k0 < 4096; k0 += 16) {
        const bool more = (k0 + 16) < 4096;
        if (more) loadAB(k0 + 16);
        tile_mma_h(sA + cur * 128 * PA2, sB + cur * 8 * PB, c, lane, wm, wn);
        if (more) storeAB(cur ^ 1);
        __syncthreads();
        cur ^= 1;
    }
#pragma unroll
    for (int mt = 0; mt < 2; mt++) {
        float s0 = 0.f, s1 = 0.f;
#pragma unroll
        for (int nt = 0; nt < 8; nt++) {
            int nc = n0 + wn * 64 + nt * 8 + (lane & 3) * 2;
            float bb0 = b1[nc], bb1 = b1[nc + 1];
            float w0 = W2[nc], w1 = W2[nc + 1];
            s0 += tanhf(c[mt][nt][0] + bb0) * w0 + tanhf(c[mt][nt][1] + bb1) * w1;
            s1 += tanhf(c[mt][nt][2] + bb0) * w0 + tanhf(c[mt][nt][3] + bb1) * w1;
        }
        s0 += __shfl_xor_sync(0xffffffffu, s0, 1); s0 += __shfl_xor_sync(0xffffffffu, s0, 2);
        s1 += __shfl_xor_sync(0xffffffffu, s1, 1); s1 += __shfl_xor_sync(0xffffffffu, s1, 2);
        if ((lane & 3) == 0) {
            int rl = wm * 32 + mt * 16 + (lane >> 2);
            sRed[wn][rl] = s0; sRed[wn][rl + 8] = s1;
        }
    }
    __syncthreads();
    if (tid < 128) g_Zp[blockIdx.y * BS + m0 + tid] = sRed[0][tid] + sRed[1][tid];
}

__global__ void __launch_bounds__(256) softmax_kernel() {
    __shared__ float red[256];
    const int b = blockIdx.x, s = threadIdx.x;
    float v = 0.f;
#pragma unroll
    for (int p = 0; p < 8; p++) v += g_Zp[p * BS + b * Ssz + s];
    red[s] = v; __syncthreads();
    for (int o = 128; o > 0; o >>= 1) { if (s < o) red[s] = fmaxf(red[s], red[s + o]); __syncthreads(); }
    float mx = red[0]; __syncthreads();
    float e = expf(v - mx);
    red[s] = e; __syncthreads();
    for (int o = 128; o > 0; o >>= 1) { if (s < o) red[s] += red[s + o]; __syncthreads(); }
    g_G[b * Ssz + s] = e / red[0];
}

// ---------------- Dr|Dw (fp16) ----------------
__global__ void __launch_bounds__(256) drw_kernel(
    const float* __restrict__ D, const float* __restrict__ Wr, const float* __restrict__ br,
    const float* __restrict__ Wx, const float* __restrict__ bx)
{
    __shared__ __align__(16) unsigned sA[2 * 128 * PA2];
    __shared__ __align__(16) unsigned sB[2 * 8 * PB];
    const int m0 = blockIdx.x * 128, n0g = blockIdx.y * 128;
    const float* W = (n0g < 1024) ? Wr : Wx;
    const float* bias = (n0g < 1024) ? br : bx;
    const int n0 = n0g & 1023;
    const int tid = threadIdx.x, lane = tid & 31, wid = tid >> 5, wm = wid & 3, wn = wid >> 2;
    float c[2][8][4];
#pragma unroll
    for (int i = 0; i < 2; i++)
#pragma unroll
        for (int j = 0; j < 8; j++)
#pragma unroll
            for (int k = 0; k < 4; k++) c[i][j][k] = 0.f;
    const int am = tid >> 1, ak = (tid & 1) * 8, ak2 = (tid & 1) * 4;
    const int kp = tid >> 5, nb = (tid & 31) * 4;
    float ra[8]; float rb0[4], rb1[4];
    auto loadAB = [&](int k0) {
        const float4* dp = (const float4*)(D + (size_t)(m0 + am) * Hsz + k0 + ak);
        float4 d0 = dp[0], d1 = dp[1];
        ra[0] = d0.x; ra[1] = d0.y; ra[2] = d0.z; ra[3] = d0.w;
        ra[4] = d1.x; ra[5] = d1.y; ra[6] = d1.z; ra[7] = d1.w;
        float4 w0 = *(const float4*)(W + (size_t)(k0 + 2 * kp) * Hsz + n0 + nb);
        float4 w1 = *(const float4*)(W + (size_t)(k0 + 2 * kp + 1) * Hsz + n0 + nb);
        rb0[0] = w0.x; rb0[1] = w0.y; rb0[2] = w0.z; rb0[3] = w0.w;
        rb1[0] = w1.x; rb1[1] = w1.y; rb1[2] = w1.z; rb1[3] = w1.w;
    };
    auto storeAB = [&](int bsel) {
        unsigned* pA = sA + bsel * 128 * PA2;
        unsigned* pB = sB + bsel * 8 * PB;
#pragma unroll
        for (int i = 0; i < 4; i++) pA[am * PA2 + ak2 + i] = h2u(ra[2 * i], ra[2 * i + 1]);
#pragma unroll
        for (int i = 0; i < 4; i++) {
            int n = nb + i;
            pB[kp * PB + (n & 7) * 16 + (n >> 3)] = h2u(rb0[i], rb1[i]);
        }
    };
    loadAB(0); storeAB(0); __syncthreads();
    int cur = 0;
    for (int k0 = 0; k0 < 1024; k0 += 16) {
        const bool more = (k0 + 16) < 1024;
        if (more) loadAB(k0 + 16);
        tile_mma_h(sA + cur * 128 * PA2, sB + cur * 8 * PB, c, lane, wm, wn);
        if (more) storeAB(cur ^ 1);
        __syncthreads();
        cur ^= 1;
    }
#pragma unroll
    for (int mt = 0; mt < 2; mt++)
#pragma unroll
        for (int nt = 0; nt < 8; nt++) {
            int nl = wn * 64 + nt * 8 + (lane & 3) * 2;
            int r0 = m0 + wm * 32 + mt * 16 + (lane >> 2);
            float bb0 = bias[n0 + nl], bb1 = bias[n0 + nl + 1];
            *(float2*)&g_Drw[(size_t)r0 * 2048 + n0g + nl] = make_float2(c[mt][nt][0] + bb0, c[mt][nt][1] + bb1);
            *(float2*)&g_Drw[(size_t)(r0 + 8) * 2048 + n0g + nl] = make_float2(c[mt][nt][2] + bb0, c[mt][nt][3] + bb1);
        }
}

// ---------------- persistent scan: fp16, ring-4, tree barrier, ldmatrix ----------------
#define R_RING 0
#define R_SW   16384
#define R_SP   (R_SW + 16384)
#define R_BIAS (R_SP + 32 * 33)
#define R_MB   (R_BIAS + 32)
#define SCAN_WORDS (R_MB + 8)
#define SCAN_SMEM  (SCAN_WORDS * 4 + 1024)

__device__ __forceinline__ void wait_par(unsigned mba, unsigned par) {
    asm volatile("{\n\t.reg .pred P1;\n\tWL_%=:\n\t"
        "mbarrier.try_wait.parity.acquire.cta.shared::cta.b64 P1, [%0], %1, 0x989680;\n\t"
        "@P1 bra.uni WD_%=;\n\tbra.uni WL_%=;\n\tWD_%=:\n\t}"
        :: "r"(mba), "r"(par) : "memory");
}

__device__ __forceinline__ void gbar_tree(int bh, int grp) {
    __syncthreads();
    if (threadIdx.x == 0) {
        __threadfence();
        unsigned g = g_gen[bh][0];
        if (atomicAdd((unsigned*)&g_grp[bh][grp][0], 1u) == 7u) {
            g_grp[bh][grp][0] = 0;
            if (atomicAdd((unsigned*)&g_root[bh][0], 1u) == 7u) {
                g_root[bh][0] = 0;
                __threadfence();
                g_gen[bh][0] = g + 1;
            } else {
                while (g_gen[bh][0] == g) __nanosleep(16);
            }
        } else {
            while (g_gen[bh][0] == g) __nanosleep(16);
        }
        __threadfence();
    }
    __syncthreads();
}

__global__ void __launch_bounds__(256, 1) scan_kernel(
    const float* __restrict__ Ur, const float* __restrict__ U,
    const float* __restrict__ bur, const float* __restrict__ bu,
    float* __restrict__ hs)
{
    extern __shared__ __align__(16) unsigned dynraw[];
    unsigned* dyn = (unsigned*)(((uintptr_t)dynraw + 1023) & ~(uintptr_t)1023);
    unsigned* ring = dyn + R_RING;
    unsigned* sW = dyn + R_SW;
    float* sP = (float*)(dyn + R_SP);
    float* sBias = (float*)(dyn + R_BIAS);
    unsigned mb0 = (unsigned)__cvta_generic_to_shared(dyn + R_MB);
    unsigned ring_u32 = (unsigned)__cvta_generic_to_shared(ring);

    const int jc = blockIdx.x & 63;
    const int bh = blockIdx.x >> 6;
    const int grp = jc >> 3;
    const int tid = threadIdx.x, lane = tid & 31, wid = tid >> 5;
    const int wm = wid & 1, wn = wid >> 1, q = lane >> 2, la3 = lane & 3;

    for (int idx = tid; idx < 16 * 1024; idx += 256) {
        int n = idx & 31, k2 = idx >> 5;
        int k = k2 * 2;
        float v0, v1;
        if (n < 16) { v0 = Ur[(size_t)k * Hsz + jc * 16 + n];       v1 = Ur[(size_t)(k + 1) * Hsz + jc * 16 + n]; }
        else        { v0 = U[(size_t)k * Hsz + jc * 16 + (n - 16)]; v1 = U[(size_t)(k + 1) * Hsz + jc * 16 + (n - 16)]; }
        sW[n * SWROW + (k2 ^ ((n & 7) << 2))] = h2u(v0, v1);
    }
    if (tid < 16)      sBias[tid] = bur[jc * 16 + tid];
    else if (tid < 32) sBias[tid] = bu[jc * 16 + tid - 16];
    if (tid == 0) {
#pragma unroll
        for (int p = 0; p < 4; p++)
            asm volatile("mbarrier.init.shared.b64 [%0], 1;" :: "r"(mb0 + p * 8) : "memory");
        asm volatile("fence.proxy.async.shared::cta;" ::: "memory");
    }
    __syncthreads();

    const int bb = tid >> 3, cp = (tid & 7) * 2;
    const int gb = bh * 32 + bb;
    const int kc_own = jc >> 4;
    const int wword = (jc & 15) * 8 + (tid & 7);
    const int wsw = (bb & 7) << 2;
    // ldmatrix lane geometry
    const int arow = wm * 16 + (lane & 15);
    const unsigned aoff = (unsigned)arow * 128;
    const int akoff = (lane >> 4) * 4;
    const int aswl = (arow & 7) << 2;
    const int brow = wn * 8 + (lane & 7);
    const unsigned boff = (unsigned)brow * SWROW;
    const int bkoff = ((lane >> 3) & 1) * 4;
    const int bswl = (lane & 7) << 2;
    float hh[2] = {0.f, 0.f};

    for (int t = 0; t < Ssz; t++) {
        const unsigned* hsrc = (const unsigned*)g_hf[(t & 1) ^ 1][bh];
        if (tid == 0) {
#pragma unroll
            for (int p = 0; p < 4; p++) {
                asm volatile("mbarrier.arrive.expect_tx.shared.b64 _, [%0], 16384;" :: "r"(mb0 + p * 8) : "memory");
                asm volatile("cp.async.bulk.shared::cta.global.mbarrier::complete_tx::bytes [%0], [%1], 16384, [%2];"
                             :: "r"(ring_u32 + p * 16384), "l"(hsrc + p * 4096), "r"(mb0 + p * 8) : "memory");
            }
        }
        const size_t rd = (size_t)gb * Ssz + t;
        float2 dr2 = __ldcg((const float2*)(g_Drw + rd * 2048 + jc * 16 + cp));
        float2 dw2 = __ldcg((const float2*)(g_Drw + rd * 2048 + 1024 + jc * 16 + cp));
        float gt = __ldcg(g_G + rd);

        float acc[4] = {0.f, 0.f, 0.f, 0.f};
#pragma unroll
        for (int cch = 0; cch < 4; cch++) {
            wait_par(mb0 + cch * 8, (unsigned)(t & 1));
            const unsigned* cb = ring + cch * 4096;
#pragma unroll
            for (int ks = 0; ks < 16; ks++) {
                int kw = ks * 8;
                unsigned a[4], bf[2];
                ldsm4(a, cb + aoff + ((kw + akoff) ^ aswl));
                ldsm2(bf, sW + boff + (((cch * 128 + kw) + bkoff) ^ bswl));
                mmah(acc, a, bf);
            }
        }
        {
            int r = wm * 16 + q;
            int c0 = wn * 8 + 2 * la3;
            sP[r * 33 + c0] = acc[0]; sP[r * 33 + c0 + 1] = acc[1];
            sP[(r + 8) * 33 + c0] = acc[2]; sP[(r + 8) * 33 + c0 + 1] = acc[3];
        }
        __syncthreads();
        {
            float dr[2] = {dr2.x, dr2.y};
            float dw[2] = {dw2.x, dw2.y};
            float2 ho;
            float* hop = &ho.x;
#pragma unroll
            for (int i = 0; i < 2; i++) {
                int cc = cp + i;
                float r = 1.f / (1.f + expf(-(dr[i] + sP[bb * 33 + cc] + sBias[cc])));
                float ht = tanhf(dw[i] + r * (sP[bb * 33 + 16 + cc] + sBias[16 + cc]));
                hh[i] = gt * ht + (1.f - gt) * hh[i];
                hop[i] = hh[i];
            }
            *(float2*)&hs[rd * Hsz + jc * 16 + cp] = ho;
            unsigned* dstT = (unsigned*)g_hf[t & 1][bh][kc_own];
            dstT[bb * 128 + (wword ^ wsw)] = h2u(hh[0], hh[1]);
        }
        gbar_tree(bh, grp);
    }
}

// ---------------- next_mem ----------------
__global__ void __launch_bounds__(256) nextmem_kernel(
    const float* __restrict__ PM, const float* __restrict__ Q,
    const float* __restrict__ Wm, const float* __restrict__ bm,
    float* __restrict__ out, const float* __restrict__ hs)
{
    __shared__ float sW6[64 * 16];
    __shared__ float sC[64 * 65];
    const int j = blockIdx.x, tid = threadIdx.x;
    const int n = tid & 15, brow = tid >> 4;
    float acc[4] = {0.f, 0.f, 0.f, 0.f};
    for (int k0 = 0; k0 < 3072; k0 += 64) {
        sW6[tid] = Wm[(size_t)(k0 + (tid >> 4)) * Hsz + j * 16 + (tid & 15)];
        sW6[tid + 256] = Wm[(size_t)(k0 + 16 + (tid >> 4)) * Hsz + j * 16 + (tid & 15)];
        sW6[tid + 512] = Wm[(size_t)(k0 + 32 + (tid >> 4)) * Hsz + j * 16 + (tid & 15)];
        sW6[tid + 768] = Wm[(size_t)(k0 + 48 + (tid >> 4)) * Hsz + j * 16 + (tid & 15)];
#pragma unroll
        for (int it = 0; it < 16; it++) {
            int idx = tid + 256 * it;
            int b = idx >> 6, kk = idx & 63, k = k0 + kk;
            float v = (k < 1024) ? PM[b * Hsz + k]
                    : (k < 2048) ? hs[((size_t)b * Ssz + 255) * Hsz + k - 1024]
                                 : Q[b * Hsz + k - 2048];
            sC[b * 65 + kk] = v;
        }
        __syncthreads();
#pragma unroll 8
        for (int kk = 0; kk < 64; kk++) {
            float w = sW6[kk * 16 + n];
            acc[0] += sC[brow * 65 + kk] * w;
            acc[1] += sC[(brow + 16) * 65 + kk] * w;
            acc[2] += sC[(brow + 32) * 65 + kk] * w;
            acc[3] += sC[(brow + 48) * 65 + kk] * w;
        }
        __syncthreads();
    }
    float bb = bm[j * 16 + n];
    out[(size_t)brow * Hsz + j * 16 + n]        = fmaxf(acc[0] + bb, 0.f);
    out[(size_t)(brow + 16) * Hsz + j * 16 + n] = fmaxf(acc[1] + bb, 0.f);
    out[(size_t)(brow + 32) * Hsz + j * 16 + n] = fmaxf(acc[2] + bb, 0.f);
    out[(size_t)(brow + 48) * Hsz + j * 16 + n] = fmaxf(acc[3] + bb, 0.f);
}

extern "C" void kernel_launch(void* const* d_in, const int* in_sizes, int n_in,
                              void* d_out, int out_size) {
    const float* D   = (const float*)d_in[0];
    const float* Q   = (const float*)d_in[1];
    const float* PM  = (const float*)d_in[2];
    const float* Wr  = (const float*)d_in[3];
    const float* br  = (const float*)d_in[4];
    const float* Ur  = (const float*)d_in[5];
    const float* bur = (const float*)d_in[6];
    const float* Wx  = (const float*)d_in[7];
    const float* bx  = (const float*)d_in[8];
    const float* U   = (const float*)d_in[9];
    const float* bu  = (const float*)d_in[10];
    const float* W1  = (const float*)d_in[11];
    const float* b1  = (const float*)d_in[12];
    const float* W2  = (const float*)d_in[13];
    const float* Wm  = (const float*)d_in[15];
    const float* bm  = (const float*)d_in[16];
    float* out = (float*)d_out;

    static int attr_done = 0;
    if (!attr_done) {
        cudaFuncSetAttribute(scan_kernel, cudaFuncAttributeMaxDynamicSharedMemorySize, SCAN_SMEM);
        attr_done = 1;
    }

    init_kernel<<<512, 256>>>();
    gate_kernel<<<dim3(128, 8), 256>>>(D, Q, PM, W1, b1, W2);
    softmax_kernel<<<64, 256>>>();
    drw_kernel<<<dim3(128, 16), 256>>>(D, Wr, br, Wx, bx);
    scan_kernel<<<NCTA, 256, SCAN_SMEM>>>(Ur, U, bur, bu, out + Bsz * Hsz);
    nextmem_kernel<<<64, 256>>>(PM, Q, Wm, bm, out, out + Bsz * Hsz);
}

// round 17
// speedup vs baseline: 1.8570x; 1.0154x over previous
#include <cuda_runtime.h>
#include <cuda_fp16.h>
#include <math.h>
#include <stdint.h>

#define Bsz 64
#define Ssz 256
#define Hsz 1024
#define BS  16384
#define NCTA 128
#define NISL 64

__device__ __align__(16) float g_Drw[(size_t)BS * 2048];
__device__ __align__(16) float g_Zp[8 * BS];
__device__ __align__(16) float g_G[BS];
__device__ __align__(256) unsigned g_hf[2][2][4][4096];
__device__ volatile unsigned g_grp[2][8][32];
__device__ volatile unsigned g_root[2][32];
__device__ volatile unsigned g_gen[2][32];

#define PA2 12
#define PB 132
#define SWROW 512

__device__ __forceinline__ void mmah(float* c, const unsigned* a, const unsigned* b) {
    asm volatile("mma.sync.aligned.m16n8k16.row.col.f32.f16.f16.f32 "
                 "{%0,%1,%2,%3},{%4,%5,%6,%7},{%8,%9},{%0,%1,%2,%3};"
                 : "+f"(c[0]), "+f"(c[1]), "+f"(c[2]), "+f"(c[3])
                 : "r"(a[0]), "r"(a[1]), "r"(a[2]), "r"(a[3]), "r"(b[0]), "r"(b[1]));
}
__device__ __forceinline__ unsigned h2u(float x, float y) {
    __half2 p = __floats2half2_rn(x, y);
    return *(unsigned*)&p;
}
__device__ __forceinline__ void ldsm4(unsigned r[4], const void* p) {
    unsigned a = (unsigned)__cvta_generic_to_shared(p);
    asm volatile("ldmatrix.sync.aligned.m8n8.x4.shared.b16 {%0,%1,%2,%3}, [%4];"
                 : "=r"(r[0]), "=r"(r[1]), "=r"(r[2]), "=r"(r[3]) : "r"(a));
}
__device__ __forceinline__ void ldsm2(unsigned r[2], const void* p) {
    unsigned a = (unsigned)__cvta_generic_to_shared(p);
    asm volatile("ldmatrix.sync.aligned.m8n8.x2.shared.b16 {%0,%1}, [%2];"
                 : "=r"(r[0]), "=r"(r[1]) : "r"(a));
}

__device__ __forceinline__ void tile_mma_h(const unsigned* sA, const unsigned* sB,
                                           float c[2][8][4], int lane, int wm, int wn) {
    const int q = lane >> 2, la3 = lane & 3;
    unsigned a[2][4];
#pragma unroll
    for (int mt = 0; mt < 2; mt++)
        ldsm4(a[mt], sA + (wm * 32 + mt * 16 + (lane & 15)) * PA2 + (lane >> 4) * 4);
    const int cb = q * 16 + wn * 8;
    uint4 b0 = *(const uint4*)&sB[la3 * PB + cb];
    uint4 b1 = *(const uint4*)&sB[la3 * PB + cb + 4];
    uint4 b2 = *(const uint4*)&sB[(la3 + 4) * PB + cb];
    uint4 b3 = *(const uint4*)&sB[(la3 + 4) * PB + cb + 4];
    unsigned bf[8][2] = {{b0.x,b2.x},{b0.y,b2.y},{b0.z,b2.z},{b0.w,b2.w},
                         {b1.x,b3.x},{b1.y,b3.y},{b1.z,b3.z},{b1.w,b3.w}};
#pragma unroll
    for (int mt = 0; mt < 2; mt++)
#pragma unroll
        for (int nt = 0; nt < 8; nt++) mmah(c[mt][nt], a[mt], bf[nt]);
}

__global__ void init_kernel() {
    int i = blockIdx.x * blockDim.x + threadIdx.x;
    if (i < 2 * 8 * 32) ((volatile unsigned*)g_grp)[i] = 0;
    if (i < 2 * 32) { ((volatile unsigned*)g_root)[i] = 0; ((volatile unsigned*)g_gen)[i] = 0; }
    if (i < 2 * 2 * 4 * 4096) ((unsigned*)g_hf)[i] = 0u;
}

// ---------------- gate GEMM (fp16, 2 CTAs/SM) ----------------
__global__ void __launch_bounds__(256, 2) gate_kernel(
    const float* __restrict__ D, const float* __restrict__ Q, const float* __restrict__ PM,
    const float* __restrict__ W1, const float* __restrict__ b1, const float* __restrict__ W2)
{
    __shared__ __align__(16) unsigned sA[2 * 128 * PA2];
    __shared__ __align__(16) unsigned sB[2 * 8 * PB];
    __shared__ float sRed[2][128];
    const int m0 = blockIdx.x * 128, n0 = blockIdx.y * 128;
    const int tid = threadIdx.x, lane = tid & 31, wid = tid >> 5, wm = wid & 3, wn = wid >> 2;
    float c[2][8][4];
#pragma unroll
    for (int i = 0; i < 2; i++)
#pragma unroll
        for (int j = 0; j < 8; j++)
#pragma unroll
            for (int k = 0; k < 4; k++) c[i][j][k] = 0.f;
    const int am = tid >> 1, ak = (tid & 1) * 8, ak2 = (tid & 1) * 4;
    const int kp = tid >> 5, nb = (tid & 31) * 4;
    float ra[8]; float rb0[4], rb1[4];
    auto loadAB = [&](int k0) {
        const int qd = k0 >> 10, kk = (k0 & 1023) + ak;
        const int r = m0 + am, b = r >> 8;
        const float4* dp = (const float4*)(D + (size_t)r * Hsz + kk);
        const float4* op = (const float4*)((((qd & 1) == 0) ? Q : PM) + (size_t)b * Hsz + kk);
        float4 d0 = dp[0], d1 = dp[1], o0 = op[0], o1 = op[1];
        if (qd < 2) {
            ra[0] = d0.x * o0.x; ra[1] = d0.y * o0.y; ra[2] = d0.z * o0.z; ra[3] = d0.w * o0.w;
            ra[4] = d1.x * o1.x; ra[5] = d1.y * o1.y; ra[6] = d1.z * o1.z; ra[7] = d1.w * o1.w;
        } else {
            ra[0] = fabsf(d0.x - o0.x); ra[1] = fabsf(d0.y - o0.y); ra[2] = fabsf(d0.z - o0.z); ra[3] = fabsf(d0.w - o0.w);
            ra[4] = fabsf(d1.x - o1.x); ra[5] = fabsf(d1.y - o1.y); ra[6] = fabsf(d1.z - o1.z); ra[7] = fabsf(d1.w - o1.w);
        }
        float4 w0 = *(const float4*)(W1 + (size_t)(k0 + 2 * kp) * Hsz + n0 + nb);
        float4 w1 = *(const float4*)(W1 + (size_t)(k0 + 2 * kp + 1) * Hsz + n0 + nb);
        rb0[0] = w0.x; rb0[1] = w0.y; rb0[2] = w0.z; rb0[3] = w0.w;
        rb1[0] = w1.x; rb1[1] = w1.y; rb1[2] = w1.z; rb1[3] = w1.w;
    };
    auto storeAB = [&](int bsel) {
        unsigned* pA = sA + bsel * 128 * PA2;
        unsigned* pB = sB + bsel * 8 * PB;
#pragma unroll
        for (int i = 0; i < 4; i++) pA[am * PA2 + ak2 + i] = h2u(ra[2 * i], ra[2 * i + 1]);
#pragma unroll
        for (int i = 0; i < 4; i++) {
            int n = nb + i;
            pB[kp * PB + (n & 7) * 16 + (n >> 3)] = h2u(rb0[i], rb1[i]);
        }
    };
    loadAB(0); storeAB(0); __syncthreads();
    int cur = 0;
    for (int k0 = 0; k0 < 4096; k0 += 16) {
        const bool more = (k0 + 16) < 4096;
        if (more) loadAB(k0 + 16);
        tile_mma_h(sA + cur * 128 * PA2, sB + cur * 8 * PB, c, lane, wm, wn);
        if (more) storeAB(cur ^ 1);
        __syncthreads();
        cur ^= 1;
    }
#pragma unroll
    for (int mt = 0; mt < 2; mt++) {
        float s0 = 0.f, s1 = 0.f;
#pragma unroll
        for (int nt = 0; nt < 8; nt++) {
            int nc = n0 + wn * 64 + nt * 8 + (lane & 3) * 2;
            float bb0 = b1[nc], bb1 = b1[nc + 1];
            float w0 = W2[nc], w1 = W2[nc + 1];
            s0 += tanhf(c[mt][nt][0] + bb0) * w0 + tanhf(c[mt][nt][1] + bb1) * w1;
            s1 += tanhf(c[mt][nt][2] + bb0) * w0 + tanhf(c[mt][nt][3] + bb1) * w1;
        }
        s0 += __shfl_xor_sync(0xffffffffu, s0, 1); s0 += __shfl_xor_sync(0xffffffffu, s0, 2);
        s1 += __shfl_xor_sync(0xffffffffu, s1, 1); s1 += __shfl_xor_sync(0xffffffffu, s1, 2);
        if ((lane & 3) == 0) {
            int rl = wm * 32 + mt * 16 + (lane >> 2);
            sRed[wn][rl] = s0; sRed[wn][rl + 8] = s1;
        }
    }
    __syncthreads();
    if (tid < 128) g_Zp[blockIdx.y * BS + m0 + tid] = sRed[0][tid] + sRed[1][tid];
}

__global__ void __launch_bounds__(256) softmax_kernel() {
    __shared__ float red[256];
    const int b = blockIdx.x, s = threadIdx.x;
    float v = 0.f;
#pragma unroll
    for (int p = 0; p < 8; p++) v += g_Zp[p * BS + b * Ssz + s];
    red[s] = v; __syncthreads();
    for (int o = 128; o > 0; o >>= 1) { if (s < o) red[s] = fmaxf(red[s], red[s + o]); __syncthreads(); }
    float mx = red[0]; __syncthreads();
    float e = expf(v - mx);
    red[s] = e; __syncthreads();
    for (int o = 128; o > 0; o >>= 1) { if (s < o) red[s] += red[s + o]; __syncthreads(); }
    g_G[b * Ssz + s] = e / red[0];
}

// ---------------- Dr|Dw (fp16, 2 CTAs/SM) ----------------
__global__ void __launch_bounds__(256, 2) drw_kernel(
    const float* __restrict__ D, const float* __restrict__ Wr, const float* __restrict__ br,
    const float* __restrict__ Wx, const float* __restrict__ bx)
{
    __shared__ __align__(16) unsigned sA[2 * 128 * PA2];
    __shared__ __align__(16) unsigned sB[2 * 8 * PB];
    const int m0 = blockIdx.x * 128, n0g = blockIdx.y * 128;
    const float* W = (n0g < 1024) ? Wr : Wx;
    const float* bias = (n0g < 1024) ? br : bx;
    const int n0 = n0g & 1023;
    const int tid = threadIdx.x, lane = tid & 31, wid = tid >> 5, wm = wid & 3, wn = wid >> 2;
    float c[2][8][4];
#pragma unroll
    for (int i = 0; i < 2; i++)
#pragma unroll
        for (int j = 0; j < 8; j++)
#pragma unroll
            for (int k = 0; k < 4; k++) c[i][j][k] = 0.f;
    const int am = tid >> 1, ak = (tid & 1) * 8, ak2 = (tid & 1) * 4;
    const int kp = tid >> 5, nb = (tid & 31) * 4;
    float ra[8]; float rb0[4], rb1[4];
    auto loadAB = [&](int k0) {
        const float4* dp = (const float4*)(D + (size_t)(m0 + am) * Hsz + k0 + ak);
        float4 d0 = dp[0], d1 = dp[1];
        ra[0] = d0.x; ra[1] = d0.y; ra[2] = d0.z; ra[3] = d0.w;
        ra[4] = d1.x; ra[5] = d1.y; ra[6] = d1.z; ra[7] = d1.w;
        float4 w0 = *(const float4*)(W + (size_t)(k0 + 2 * kp) * Hsz + n0 + nb);
        float4 w1 = *(const float4*)(W + (size_t)(k0 + 2 * kp + 1) * Hsz + n0 + nb);
        rb0[0] = w0.x; rb0[1] = w0.y; rb0[2] = w0.z; rb0[3] = w0.w;
        rb1[0] = w1.x; rb1[1] = w1.y; rb1[2] = w1.z; rb1[3] = w1.w;
    };
    auto storeAB = [&](int bsel) {
        unsigned* pA = sA + bsel * 128 * PA2;
        unsigned* pB = sB + bsel * 8 * PB;
#pragma unroll
        for (int i = 0; i < 4; i++) pA[am * PA2 + ak2 + i] = h2u(ra[2 * i], ra[2 * i + 1]);
#pragma unroll
        for (int i = 0; i < 4; i++) {
            int n = nb + i;
            pB[kp * PB + (n & 7) * 16 + (n >> 3)] = h2u(rb0[i], rb1[i]);
        }
    };
    loadAB(0); storeAB(0); __syncthreads();
    int cur = 0;
    for (int k0 = 0; k0 < 1024; k0 += 16) {
        const bool more = (k0 + 16) < 1024;
        if (more) loadAB(k0 + 16);
        tile_mma_h(sA + cur * 128 * PA2, sB + cur * 8 * PB, c, lane, wm, wn);
        if (more) storeAB(cur ^ 1);
        __syncthreads();
        cur ^= 1;
    }
#pragma unroll
    for (int mt = 0; mt < 2; mt++)
#pragma unroll
        for (int nt = 0; nt < 8; nt++) {
            int nl = wn * 64 + nt * 8 + (lane & 3) * 2;
            int r0 = m0 + wm * 32 + mt * 16 + (lane >> 2);
            float bb0 = bias[n0 + nl], bb1 = bias[n0 + nl + 1];
            *(float2*)&g_Drw[(size_t)r0 * 2048 + n0g + nl] = make_float2(c[mt][nt][0] + bb0, c[mt][nt][1] + bb1);
            *(float2*)&g_Drw[(size_t)(r0 + 8) * 2048 + n0g + nl] = make_float2(c[mt][nt][2] + bb0, c[mt][nt][3] + bb1);
        }
}

// ---------------- persistent scan: fp16, ring-4, tree barrier, ldmatrix, dual acc ----------------
#define R_RING 0
#define R_SW   16384
#define R_SP   (R_SW + 16384)
#define R_BIAS (R_SP + 32 * 33)
#define R_MB   (R_BIAS + 32)
#define SCAN_WORDS (R_MB + 8)
#define SCAN_SMEM  (SCAN_WORDS * 4 + 1024)

__device__ __forceinline__ void wait_par(unsigned mba, unsigned par) {
    asm volatile("{\n\t.reg .pred P1;\n\tWL_%=:\n\t"
        "mbarrier.try_wait.parity.acquire.cta.shared::cta.b64 P1, [%0], %1, 0x989680;\n\t"
        "@P1 bra.uni WD_%=;\n\tbra.uni WL_%=;\n\tWD_%=:\n\t}"
        :: "r"(mba), "r"(par) : "memory");
}

__device__ __forceinline__ void gbar_tree(int bh, int grp) {
    __syncthreads();
    if (threadIdx.x == 0) {
        __threadfence();
        unsigned g = g_gen[bh][0];
        if (atomicAdd((unsigned*)&g_grp[bh][grp][0], 1u) == 7u) {
            g_grp[bh][grp][0] = 0;
            if (atomicAdd((unsigned*)&g_root[bh][0], 1u) == 7u) {
                g_root[bh][0] = 0;
                __threadfence();
                g_gen[bh][0] = g + 1;
            } else {
                while (g_gen[bh][0] == g) __nanosleep(16);
            }
        } else {
            while (g_gen[bh][0] == g) __nanosleep(16);
        }
        __threadfence();
    }
    __syncthreads();
}

__global__ void __launch_bounds__(256, 1) scan_kernel(
    const float* __restrict__ Ur, const float* __restrict__ U,
    const float* __restrict__ bur, const float* __restrict__ bu,
    float* __restrict__ hs)
{
    extern __shared__ __align__(16) unsigned dynraw[];
    unsigned* dyn = (unsigned*)(((uintptr_t)dynraw + 1023) & ~(uintptr_t)1023);
    unsigned* ring = dyn + R_RING;
    unsigned* sW = dyn + R_SW;
    float* sP = (float*)(dyn + R_SP);
    float* sBias = (float*)(dyn + R_BIAS);
    unsigned mb0 = (unsigned)__cvta_generic_to_shared(dyn + R_MB);
    unsigned ring_u32 = (unsigned)__cvta_generic_to_shared(ring);

    const int jc = blockIdx.x & 63;
    const int bh = blockIdx.x >> 6;
    const int grp = jc >> 3;
    const int tid = threadIdx.x, lane = tid & 31, wid = tid >> 5;
    const int wm = wid & 1, wn = wid >> 1, q = lane >> 2, la3 = lane & 3;

    for (int idx = tid; idx < 16 * 1024; idx += 256) {
        int n = idx & 31, k2 = idx >> 5;
        int k = k2 * 2;
        float v0, v1;
        if (n < 16) { v0 = Ur[(size_t)k * Hsz + jc * 16 + n];       v1 = Ur[(size_t)(k + 1) * Hsz + jc * 16 + n]; }
        else        { v0 = U[(size_t)k * Hsz + jc * 16 + (n - 16)]; v1 = U[(size_t)(k + 1) * Hsz + jc * 16 + (n - 16)]; }
        sW[n * SWROW + (k2 ^ ((n & 7) << 2))] = h2u(v0, v1);
    }
    if (tid < 16)      sBias[tid] = bur[jc * 16 + tid];
    else if (tid < 32) sBias[tid] = bu[jc * 16 + tid - 16];
    if (tid == 0) {
#pragma unroll
        for (int p = 0; p < 4; p++)
            asm volatile("mbarrier.init.shared.b64 [%0], 1;" :: "r"(mb0 + p * 8) : "memory");
        asm volatile("fence.proxy.async.shared::cta;" ::: "memory");
    }
    __syncthreads();

    const int bb = tid >> 3, cp = (tid & 7) * 2;
    const int gb = bh * 32 + bb;
    const int kc_own = jc >> 4;
    const int wword = (jc & 15) * 8 + (tid & 7);
    const int wsw = (bb & 7) << 2;
    const int arow = wm * 16 + (lane & 15);
    const unsigned aoff = (unsigned)arow * 128;
    const int akoff = (lane >> 4) * 4;
    const int aswl = (arow & 7) << 2;
    const int brow = wn * 8 + (lane & 7);
    const unsigned boff = (unsigned)brow * SWROW;
    const int bkoff = ((lane >> 3) & 1) * 4;
    const int bswl = (lane & 7) << 2;
    float hh[2] = {0.f, 0.f};

    for (int t = 0; t < Ssz; t++) {
        const unsigned* hsrc = (const unsigned*)g_hf[(t & 1) ^ 1][bh];
        if (tid == 0) {
#pragma unroll
            for (int p = 0; p < 4; p++) {
                asm volatile("mbarrier.arrive.expect_tx.shared.b64 _, [%0], 16384;" :: "r"(mb0 + p * 8) : "memory");
                asm volatile("cp.async.bulk.shared::cta.global.mbarrier::complete_tx::bytes [%0], [%1], 16384, [%2];"
                             :: "r"(ring_u32 + p * 16384), "l"(hsrc + p * 4096), "r"(mb0 + p * 8) : "memory");
            }
        }
        const size_t rd = (size_t)gb * Ssz + t;
        float2 dr2 = __ldcg((const float2*)(g_Drw + rd * 2048 + jc * 16 + cp));
        float2 dw2 = __ldcg((const float2*)(g_Drw + rd * 2048 + 1024 + jc * 16 + cp));
        float gt = __ldcg(g_G + rd);

        float accA[4] = {0.f, 0.f, 0.f, 0.f};
        float accB[4] = {0.f, 0.f, 0.f, 0.f};
#pragma unroll
        for (int cch = 0; cch < 4; cch++) {
            wait_par(mb0 + cch * 8, (unsigned)(t & 1));
            const unsigned* cb = ring + cch * 4096;
#pragma unroll
            for (int ks = 0; ks < 16; ks += 2) {
                unsigned a0[4], b0f[2], a1[4], b1f[2];
                int kw0 = ks * 8, kw1 = kw0 + 8;
                ldsm4(a0, cb + aoff + ((kw0 + akoff) ^ aswl));
                ldsm2(b0f, sW + boff + (((cch * 128 + kw0) + bkoff) ^ bswl));
                ldsm4(a1, cb + aoff + ((kw1 + akoff) ^ aswl));
                ldsm2(b1f, sW + boff + (((cch * 128 + kw1) + bkoff) ^ bswl));
                mmah(accA, a0, b0f);
                mmah(accB, a1, b1f);
            }
        }
#pragma unroll
        for (int i = 0; i < 4; i++) accA[i] += accB[i];
        {
            int r = wm * 16 + q;
            int c0 = wn * 8 + 2 * la3;
            sP[r * 33 + c0] = accA[0]; sP[r * 33 + c0 + 1] = accA[1];
            sP[(r + 8) * 33 + c0] = accA[2]; sP[(r + 8) * 33 + c0 + 1] = accA[3];
        }
        __syncthreads();
        {
            float dr[2] = {dr2.x, dr2.y};
            float dw[2] = {dw2.x, dw2.y};
            float2 ho;
            float* hop = &ho.x;
#pragma unroll
            for (int i = 0; i < 2; i++) {
                int cc = cp + i;
                float r = 1.f / (1.f + expf(-(dr[i] + sP[bb * 33 + cc] + sBias[cc])));
                float ht = tanhf(dw[i] + r * (sP[bb * 33 + 16 + cc] + sBias[16 + cc]));
                hh[i] = gt * ht + (1.f - gt) * hh[i];
                hop[i] = hh[i];
            }
            *(float2*)&hs[rd * Hsz + jc * 16 + cp] = ho;
            unsigned* dstT = (unsigned*)g_hf[t & 1][bh][kc_own];
            dstT[bb * 128 + (wword ^ wsw)] = h2u(hh[0], hh[1]);
        }
        gbar_tree(bh, grp);
    }
}

// ---------------- next_mem ----------------
__global__ void __launch_bounds__(256) nextmem_kernel(
    const float* __restrict__ PM, const float* __restrict__ Q,
    const float* __restrict__ Wm, const float* __restrict__ bm,
    float* __restrict__ out, const float* __restrict__ hs)
{
    __shared__ float sW6[64 * 16];
    __shared__ float sC[64 * 65];
    const int j = blockIdx.x, tid = threadIdx.x;
    const int n = tid & 15, brow = tid >> 4;
    float acc[4] = {0.f, 0.f, 0.f, 0.f};
    for (int k0 = 0; k0 < 3072; k0 += 64) {
        sW6[tid] = Wm[(size_t)(k0 + (tid >> 4)) * Hsz + j * 16 + (tid & 15)];
        sW6[tid + 256] = Wm[(size_t)(k0 + 16 + (tid >> 4)) * Hsz + j * 16 + (tid & 15)];
        sW6[tid + 512] = Wm[(size_t)(k0 + 32 + (tid >> 4)) * Hsz + j * 16 + (tid & 15)];
        sW6[tid + 768] = Wm[(size_t)(k0 + 48 + (tid >> 4)) * Hsz + j * 16 + (tid & 15)];
#pragma unroll
        for (int it = 0; it < 16; it++) {
            int idx = tid + 256 * it;
            int b = idx >> 6, kk = idx & 63, k = k0 + kk;
            float v = (k < 1024) ? PM[b * Hsz + k]
                    : (k < 2048) ? hs[((size_t)b * Ssz + 255) * Hsz + k - 1024]
                                 : Q[b * Hsz + k - 2048];
            sC[b * 65 + kk] = v;
        }
        __syncthreads();
#pragma unroll 8
        for (int kk = 0; kk < 64; kk++) {
            float w = sW6[kk * 16 + n];
            acc[0] += sC[brow * 65 + kk] * w;
            acc[1] += sC[(brow + 16) * 65 + kk] * w;
            acc[2] += sC[(brow + 32) * 65 + kk] * w;
            acc[3] += sC[(brow + 48) * 65 + kk] * w;
        }
        __syncthreads();
    }
    float bb = bm[j * 16 + n];
    out[(size_t)brow * Hsz + j * 16 + n]        = fmaxf(acc[0] + bb, 0.f);
    out[(size_t)(brow + 16) * Hsz + j * 16 + n] = fmaxf(acc[1] + bb, 0.f);
    out[(size_t)(brow + 32) * Hsz + j * 16 + n] = fmaxf(acc[2] + bb, 0.f);
    out[(size_t)(brow + 48) * Hsz + j * 16 + n] = fmaxf(acc[3] + bb, 0.f);
}

extern "C" void kernel_launch(void* const* d_in, const int* in_sizes, int n_in,
                              void* d_out, int out_size) {
    const float* D   = (const float*)d_in[0];
    const float* Q   = (const float*)d_in[1];
    const float* PM  = (const float*)d_in[2];
    const float* Wr  = (const float*)d_in[3];
    const float* br  = (const float*)d_in[4];
    const float* Ur  = (const float*)d_in[5];
    const float* bur = (const float*)d_in[6];
    const float* Wx  = (const float*)d_in[7];
    const float* bx  = (const float*)d_in[8];
    const float* U   = (const float*)d_in[9];
    const float* bu  = (const float*)d_in[10];
    const float* W1  = (const float*)d_in[11];
    const float* b1  = (const float*)d_in[12];
    const float* W2  = (const float*)d_in[13];
    const float* Wm  = (const float*)d_in[15];
    const float* bm  = (const float*)d_in[16];
    float* out = (float*)d_out;

    static int attr_done = 0;
    if (!attr_done) {
        cudaFuncSetAttribute(scan_kernel, cudaFuncAttributeMaxDynamicSharedMemorySize, SCAN_SMEM);
        attr_done = 1;
    }

    init_kernel<<<512, 256>>>();
    gate_kernel<<<dim3(128, 8), 256>>>(D, Q, PM, W1, b1, W2);
    softmax_kernel<<<64, 256>>>();
    drw_kernel<<<dim3(128, 16), 256>>>(D, Wr, br, Wx, bx);
    scan_kernel<<<NCTA, 256, SCAN_SMEM>>>(Ur, U, bur, bu, out + Bsz * Hsz);
    nextmem_kernel<<<64, 256>>>(PM, Q, Wm, bm, out, out + Bsz * Hsz);
}